// round 1
// baseline (speedup 1.0000x reference)
#include <cuda_runtime.h>
#include <math.h>

#define D_MODEL 1024
#define D_STATE 16
#define D_CONV  4
#define D_INNER 2048
#define BSZ     2
#define LEN     1024
#define M_TOT   (BSZ*LEN)        // 2048 rows (b*L + l)
#define NPROJ   (2*D_STATE+1)    // 33

// ---------------- scratch (static device buffers; no allocation) ------------
__device__ float g_xz[(size_t)M_TOT * 2 * D_INNER];   // [2048][4096]  (x_ssm | z)
__device__ float g_xc[(size_t)M_TOT * D_INNER];       // [2048][2048]  conv+silu out
__device__ float g_proj[(size_t)M_TOT * NPROJ];       // [2048][33]
__device__ float g_Y[(size_t)M_TOT * D_INNER];        // [2048][2048]  pre-out-proj

// ---------------- SGEMM (NT): C[M,N] = A[M,K] * B[N,K]^T --------------------
// BM=BN=128, BK=8, 256 threads, 8x8 per-thread microtile.
// Requires: M % 128 == 0, K % 8 == 0, K % 4 == 0 (float4 loads). N guarded.
__global__ void __launch_bounds__(256, 2)
sgemm_nt(const float* __restrict__ A, const float* __restrict__ B,
         float* __restrict__ C, int M, int N, int K)
{
    const int BM = 128, BN = 128, BK = 8, TM = 8, TN = 8;
    __shared__ float As[BK][BM];
    __shared__ float Bs[BK][BN];

    const int tid = threadIdx.x;
    const int bx = blockIdx.x;   // N tiles
    const int by = blockIdx.y;   // M tiles

    const int tr = tid / 16;     // 0..15  (row group)
    const int tc = tid % 16;     // 0..15  (col group)

    const int a_row = tid >> 1;            // 0..127
    const int a_col = (tid & 1) * 4;       // 0 or 4

    const float* Ab = A + (size_t)(by * BM) * K;
    const float* Bb = B + (size_t)(bx * BN) * K;

    float acc[TM][TN];
    #pragma unroll
    for (int i = 0; i < TM; i++)
        #pragma unroll
        for (int j = 0; j < TN; j++) acc[i][j] = 0.f;

    for (int k0 = 0; k0 < K; k0 += BK) {
        // load A tile (128x8) -> As[k][m]
        float4 av = *(const float4*)(Ab + (size_t)a_row * K + k0 + a_col);
        As[a_col + 0][a_row] = av.x;
        As[a_col + 1][a_row] = av.y;
        As[a_col + 2][a_row] = av.z;
        As[a_col + 3][a_row] = av.w;
        // load B tile (128x8) -> Bs[k][n], guard N
        float4 bv = make_float4(0.f, 0.f, 0.f, 0.f);
        if (bx * BN + a_row < N)
            bv = *(const float4*)(Bb + (size_t)a_row * K + k0 + a_col);
        Bs[a_col + 0][a_row] = bv.x;
        Bs[a_col + 1][a_row] = bv.y;
        Bs[a_col + 2][a_row] = bv.z;
        Bs[a_col + 3][a_row] = bv.w;
        __syncthreads();

        #pragma unroll
        for (int k = 0; k < BK; k++) {
            float ar[TM], br[TN];
            #pragma unroll
            for (int i = 0; i < TM; i++) ar[i] = As[k][tr * TM + i];
            #pragma unroll
            for (int j = 0; j < TN; j++) br[j] = Bs[k][tc * TN + j];
            #pragma unroll
            for (int i = 0; i < TM; i++)
                #pragma unroll
                for (int j = 0; j < TN; j++)
                    acc[i][j] = fmaf(ar[i], br[j], acc[i][j]);
        }
        __syncthreads();
    }

    #pragma unroll
    for (int i = 0; i < TM; i++) {
        int row = by * BM + tr * TM + i;
        #pragma unroll
        for (int j = 0; j < TN; j++) {
            int col = bx * BN + tc * TN + j;
            if (col < N) C[(size_t)row * N + col] = acc[i][j];
        }
    }
}

// ---------------- causal depthwise conv (K=4) + SiLU ------------------------
__global__ void conv_silu_kernel(const float* __restrict__ xz,
                                 const float* __restrict__ cw,
                                 const float* __restrict__ cb,
                                 float* __restrict__ xc)
{
    int idx = blockIdx.x * blockDim.x + threadIdx.x;   // over M_TOT*D_INNER
    if (idx >= M_TOT * D_INNER) return;
    int d = idx & (D_INNER - 1);
    int m = idx >> 11;           // / D_INNER
    int l = m & (LEN - 1);

    const float w0 = cw[d * 4 + 0], w1 = cw[d * 4 + 1];
    const float w2 = cw[d * 4 + 2], w3 = cw[d * 4 + 3];
    const float* base = xz + (size_t)m * (2 * D_INNER) + d;
    const int stride = 2 * D_INNER;

    float acc = cb[d] + w3 * base[0];               // w[3] * x[l]
    if (l >= 1) acc += w2 * base[-stride];          // w[2] * x[l-1]
    if (l >= 2) acc += w1 * base[-2 * stride];      // w[1] * x[l-2]
    if (l >= 3) acc += w0 * base[-3 * stride];      // w[0] * x[l-3]

    float sig = 1.f / (1.f + __expf(-acc));
    xc[idx] = acc * sig;
}

// ---------------- x-proj: proj[M,33] = xc[M,2048] * W_x[33,2048]^T ----------
// warp-per-row; 33 accumulators per lane; butterfly reduce.
__global__ void __launch_bounds__(256)
xproj_kernel(const float* __restrict__ xc, const float* __restrict__ Wx,
             float* __restrict__ proj)
{
    int warp = (blockIdx.x * blockDim.x + threadIdx.x) >> 5;
    int lane = threadIdx.x & 31;
    if (warp >= M_TOT) return;

    const float* xr = xc + (size_t)warp * D_INNER;
    float acc[NPROJ];
    #pragma unroll
    for (int e = 0; e < NPROJ; e++) acc[e] = 0.f;

    for (int k = lane; k < D_INNER; k += 32) {
        float xv = xr[k];
        #pragma unroll
        for (int e = 0; e < NPROJ; e++)
            acc[e] = fmaf(xv, Wx[(size_t)e * D_INNER + k], acc[e]);
    }
    #pragma unroll
    for (int e = 0; e < NPROJ; e++) {
        float v = acc[e];
        v += __shfl_xor_sync(0xffffffffu, v, 16);
        v += __shfl_xor_sync(0xffffffffu, v, 8);
        v += __shfl_xor_sync(0xffffffffu, v, 4);
        v += __shfl_xor_sync(0xffffffffu, v, 2);
        v += __shfl_xor_sync(0xffffffffu, v, 1);
        if (lane == (e & 31)) proj[(size_t)warp * NPROJ + e] = v;
    }
}

// ---------------- selective scan + gating ----------------------------------
// warp handles 2 channels d; lanes 0-15 states of d0, 16-31 states of d1.
__global__ void __launch_bounds__(256)
scan_kernel(const float* __restrict__ proj, const float* __restrict__ xc,
            const float* __restrict__ xz,
            const float* __restrict__ dt_w, const float* __restrict__ dt_b,
            const float* __restrict__ A_log, const float* __restrict__ Dp,
            float* __restrict__ Y)
{
    int warp = (blockIdx.x * blockDim.x + threadIdx.x) >> 5;
    int lane = threadIdx.x & 31;
    int n    = lane & 15;
    int dpair = warp * 2 + (lane >> 4);   // 0..4095 = b*D_INNER + d
    if (dpair >= BSZ * D_INNER) return;
    int b = dpair >> 11;
    int d = dpair & (D_INNER - 1);

    const float An  = -expf(A_log[d * D_STATE + n]);
    const float dtw = dt_w[d];
    const float dtb = dt_b[d];
    const float Dd  = Dp[d];

    float h = 0.f;
    const int base = b * LEN;

    for (int t = 0; t < LEN; t++) {
        const int m = base + t;
        const float* pr = proj + (size_t)m * NPROJ;
        float dtraw = pr[0];
        float Bn    = pr[1 + n];
        float Cn    = pr[1 + D_STATE + n];
        float xcv   = xc[(size_t)m * D_INNER + d];
        float zv    = xz[(size_t)m * (2 * D_INNER) + D_INNER + d];

        float s  = fmaf(dtraw, dtw, dtb);
        float dt = (s > 20.f) ? s : log1pf(__expf(s));
        float dA = __expf(dt * An);
        h = fmaf(dA, h, dt * Bn * xcv);

        float yp = h * Cn;
        yp += __shfl_xor_sync(0xffffffffu, yp, 8);
        yp += __shfl_xor_sync(0xffffffffu, yp, 4);
        yp += __shfl_xor_sync(0xffffffffu, yp, 2);
        yp += __shfl_xor_sync(0xffffffffu, yp, 1);

        if (n == 0) {
            float sig = 1.f / (1.f + __expf(-zv));
            Y[(size_t)m * D_INNER + d] = (yp + xcv * Dd) * (zv * sig);
        }
    }
}

// ---------------- launch -----------------------------------------------------
extern "C" void kernel_launch(void* const* d_in, const int* in_sizes, int n_in,
                              void* d_out, int out_size)
{
    const float* x      = (const float*)d_in[0];
    const float* W_in   = (const float*)d_in[1];
    const float* conv_w = (const float*)d_in[2];
    const float* conv_b = (const float*)d_in[3];
    const float* W_x    = (const float*)d_in[4];
    const float* dt_w   = (const float*)d_in[5];
    const float* dt_b   = (const float*)d_in[6];
    const float* A_log  = (const float*)d_in[7];
    const float* D_par  = (const float*)d_in[8];
    const float* W_out  = (const float*)d_in[9];
    float* out = (float*)d_out;

    float *xz, *xc, *proj, *Y;
    cudaGetSymbolAddress((void**)&xz,   g_xz);
    cudaGetSymbolAddress((void**)&xc,   g_xc);
    cudaGetSymbolAddress((void**)&proj, g_proj);
    cudaGetSymbolAddress((void**)&Y,    g_Y);

    // 1) xz = x @ W_in^T : M=2048, N=4096, K=1024
    {
        dim3 grid(2 * D_INNER / 128, M_TOT / 128);
        sgemm_nt<<<grid, 256>>>(x, W_in, xz, M_TOT, 2 * D_INNER, D_MODEL);
    }
    // 2) conv + silu
    {
        int total = M_TOT * D_INNER;
        conv_silu_kernel<<<(total + 255) / 256, 256>>>(xz, conv_w, conv_b, xc);
    }
    // 3) proj = xc @ W_x^T : warp per row
    {
        xproj_kernel<<<M_TOT / 8, 256>>>(xc, W_x, proj);
    }
    // 4) selective scan + gating -> Y
    {
        // 2048 warps needed: 256 blocks x 8 warps
        scan_kernel<<<(BSZ * D_INNER / 2) / 8, 256>>>(proj, xc, xz, dt_w, dt_b,
                                                      A_log, D_par, Y);
    }
    // 5) out = Y @ W_out^T : M=2048, N=1024, K=2048
    {
        dim3 grid(D_MODEL / 128, M_TOT / 128);
        sgemm_nt<<<grid, 256>>>(Y, W_out, out, M_TOT, D_MODEL, D_INNER);
    }
}

// round 2
// speedup vs baseline: 1.1570x; 1.1570x over previous
#include <cuda_runtime.h>
#include <math.h>

#define D_MODEL 1024
#define D_STATE 16
#define D_CONV  4
#define D_INNER 2048
#define BSZ     2
#define LEN     1024
#define M_TOT   (BSZ*LEN)        // 2048 rows (b*L + l)
#define NPROJ   (2*D_STATE+1)    // 33
#define CHUNKS  8
#define CHUNK_T (LEN/CHUNKS)     // 128

// ---------------- scratch (static device buffers; no allocation) ------------
__device__ float g_xz[(size_t)M_TOT * 2 * D_INNER];   // [2048][4096]  (x_ssm | z)
__device__ float g_xc[(size_t)M_TOT * D_INNER];       // [2048][2048]  conv+silu out
__device__ float g_proj[(size_t)M_TOT * NPROJ];       // [2048][33]
__device__ float g_Y[(size_t)M_TOT * D_INNER];        // [2048][2048]  pre-out-proj
// chunked-scan scratch: [B][CHUNKS][D_INNER][D_STATE]
__device__ float g_P [(size_t)BSZ * CHUNKS * D_INNER * D_STATE];
__device__ float g_Qc[(size_t)BSZ * CHUNKS * D_INNER * D_STATE];
__device__ float g_H [(size_t)BSZ * CHUNKS * D_INNER * D_STATE];

// ---------------- SGEMM (NT): C[M,N] = A[M,K] * B[N,K]^T --------------------
__global__ void __launch_bounds__(256, 2)
sgemm_nt(const float* __restrict__ A, const float* __restrict__ B,
         float* __restrict__ C, int M, int N, int K)
{
    const int BM = 128, BN = 128, BK = 8, TM = 8, TN = 8;
    __shared__ float As[BK][BM];
    __shared__ float Bs[BK][BN];

    const int tid = threadIdx.x;
    const int bx = blockIdx.x;   // N tiles
    const int by = blockIdx.y;   // M tiles

    const int tr = tid / 16;     // 0..15
    const int tc = tid % 16;     // 0..15

    const int a_row = tid >> 1;            // 0..127
    const int a_col = (tid & 1) * 4;       // 0 or 4

    const float* Ab = A + (size_t)(by * BM) * K;
    const float* Bb = B + (size_t)(bx * BN) * K;

    float acc[TM][TN];
    #pragma unroll
    for (int i = 0; i < TM; i++)
        #pragma unroll
        for (int j = 0; j < TN; j++) acc[i][j] = 0.f;

    for (int k0 = 0; k0 < K; k0 += BK) {
        float4 av = *(const float4*)(Ab + (size_t)a_row * K + k0 + a_col);
        As[a_col + 0][a_row] = av.x;
        As[a_col + 1][a_row] = av.y;
        As[a_col + 2][a_row] = av.z;
        As[a_col + 3][a_row] = av.w;
        float4 bv = make_float4(0.f, 0.f, 0.f, 0.f);
        if (bx * BN + a_row < N)
            bv = *(const float4*)(Bb + (size_t)a_row * K + k0 + a_col);
        Bs[a_col + 0][a_row] = bv.x;
        Bs[a_col + 1][a_row] = bv.y;
        Bs[a_col + 2][a_row] = bv.z;
        Bs[a_col + 3][a_row] = bv.w;
        __syncthreads();

        #pragma unroll
        for (int k = 0; k < BK; k++) {
            float ar[TM], br[TN];
            #pragma unroll
            for (int i = 0; i < TM; i++) ar[i] = As[k][tr * TM + i];
            #pragma unroll
            for (int j = 0; j < TN; j++) br[j] = Bs[k][tc * TN + j];
            #pragma unroll
            for (int i = 0; i < TM; i++)
                #pragma unroll
                for (int j = 0; j < TN; j++)
                    acc[i][j] = fmaf(ar[i], br[j], acc[i][j]);
        }
        __syncthreads();
    }

    #pragma unroll
    for (int i = 0; i < TM; i++) {
        int row = by * BM + tr * TM + i;
        #pragma unroll
        for (int j = 0; j < TN; j++) {
            int col = bx * BN + tc * TN + j;
            if (col < N) C[(size_t)row * N + col] = acc[i][j];
        }
    }
}

// ---------------- causal depthwise conv (K=4) + SiLU ------------------------
__global__ void conv_silu_kernel(const float* __restrict__ xz,
                                 const float* __restrict__ cw,
                                 const float* __restrict__ cb,
                                 float* __restrict__ xc)
{
    int idx = blockIdx.x * blockDim.x + threadIdx.x;
    if (idx >= M_TOT * D_INNER) return;
    int d = idx & (D_INNER - 1);
    int m = idx >> 11;
    int l = m & (LEN - 1);

    const float w0 = cw[d * 4 + 0], w1 = cw[d * 4 + 1];
    const float w2 = cw[d * 4 + 2], w3 = cw[d * 4 + 3];
    const float* base = xz + (size_t)m * (2 * D_INNER) + d;
    const int stride = 2 * D_INNER;

    float acc = cb[d] + w3 * base[0];
    if (l >= 1) acc += w2 * base[-stride];
    if (l >= 2) acc += w1 * base[-2 * stride];
    if (l >= 3) acc += w0 * base[-3 * stride];

    float sig = 1.f / (1.f + __expf(-acc));
    xc[idx] = acc * sig;
}

// ---------------- x-proj: proj[M,33] = xc[M,2048] * W_x[33,2048]^T ----------
__global__ void __launch_bounds__(256)
xproj_kernel(const float* __restrict__ xc, const float* __restrict__ Wx,
             float* __restrict__ proj)
{
    int warp = (blockIdx.x * blockDim.x + threadIdx.x) >> 5;
    int lane = threadIdx.x & 31;
    if (warp >= M_TOT) return;

    const float* xr = xc + (size_t)warp * D_INNER;
    float acc[NPROJ];
    #pragma unroll
    for (int e = 0; e < NPROJ; e++) acc[e] = 0.f;

    for (int k = lane; k < D_INNER; k += 32) {
        float xv = xr[k];
        #pragma unroll
        for (int e = 0; e < NPROJ; e++)
            acc[e] = fmaf(xv, Wx[(size_t)e * D_INNER + k], acc[e]);
    }
    #pragma unroll
    for (int e = 0; e < NPROJ; e++) {
        float v = acc[e];
        v += __shfl_xor_sync(0xffffffffu, v, 16);
        v += __shfl_xor_sync(0xffffffffu, v, 8);
        v += __shfl_xor_sync(0xffffffffu, v, 4);
        v += __shfl_xor_sync(0xffffffffu, v, 2);
        v += __shfl_xor_sync(0xffffffffu, v, 1);
        if (lane == (e & 31)) proj[(size_t)warp * NPROJ + e] = v;
    }
}

// ---------------- chunked selective scan -------------------------------------
// Recurrence per (b,d,n): h_t = dA_t * h_{t-1} + dt_t*B_tn*xc_t  (associative)
// Pass 1: per chunk, compute transfer (P = prod dA, q = scan from h=0).
// Pass 2: sequential combine over CHUNKS -> chunk start states H.
// Pass 3: re-run each chunk from H, emit y + gating.
// Warp layout (pass 1/3): lanes 0-15 = states of channel d0, 16-31 = d1.

__global__ void __launch_bounds__(256)
scan_pass1(const float* __restrict__ proj, const float* __restrict__ xc,
           const float* __restrict__ dt_w, const float* __restrict__ dt_b,
           const float* __restrict__ A_log,
           float* __restrict__ P, float* __restrict__ Q)
{
    int wg   = (blockIdx.x * blockDim.x + threadIdx.x) >> 5;
    int lane = threadIdx.x & 31;
    int n    = lane & 15;
    int pair = wg >> 3;            // / CHUNKS
    int c    = wg & (CHUNKS - 1);
    if (pair >= BSZ * D_INNER / 2) return;
    int q  = pair * 2 + (lane >> 4);
    int b  = q >> 11;
    int d  = q & (D_INNER - 1);

    const float An  = -expf(A_log[d * D_STATE + n]);
    const float dtw = dt_w[d];
    const float dtb = dt_b[d];

    float Pp = 1.f, acc = 0.f;
    const int t0 = c * CHUNK_T;
    const float* pr0 = proj + (size_t)(b * LEN + t0) * NPROJ;
    const float* xc0 = xc + (size_t)(b * LEN + t0) * D_INNER + d;

    #pragma unroll 2
    for (int t = 0; t < CHUNK_T; t++) {
        const float* pr = pr0 + (size_t)t * NPROJ;
        float dtraw = pr[0];
        float Bn    = pr[1 + n];
        float xcv   = xc0[(size_t)t * D_INNER];

        float s  = fmaf(dtraw, dtw, dtb);
        float dt = (s > 20.f) ? s : log1pf(__expf(s));
        float dA = __expf(dt * An);
        acc = fmaf(dA, acc, dt * Bn * xcv);
        Pp *= dA;
    }
    size_t o = ((size_t)((b * CHUNKS + c) * D_INNER) + d) * D_STATE + n;
    P[o] = Pp;
    Q[o] = acc;
}

__global__ void __launch_bounds__(256)
scan_pass2(const float* __restrict__ P, const float* __restrict__ Q,
           float* __restrict__ H)
{
    int i = blockIdx.x * blockDim.x + threadIdx.x;   // (b*D_INNER + d)*16 + n
    if (i >= BSZ * D_INNER * D_STATE) return;
    int n = i & 15;
    int d = (i >> 4) & (D_INNER - 1);
    int b = i >> 15;

    float h = 0.f;
    #pragma unroll
    for (int c = 0; c < CHUNKS; c++) {
        size_t o = ((size_t)((b * CHUNKS + c) * D_INNER) + d) * D_STATE + n;
        H[o] = h;
        h = fmaf(P[o], h, Q[o]);
    }
}

__global__ void __launch_bounds__(256)
scan_pass3(const float* __restrict__ proj, const float* __restrict__ xc,
           const float* __restrict__ xz,
           const float* __restrict__ dt_w, const float* __restrict__ dt_b,
           const float* __restrict__ A_log, const float* __restrict__ Dp,
           const float* __restrict__ H, float* __restrict__ Y)
{
    int wg   = (blockIdx.x * blockDim.x + threadIdx.x) >> 5;
    int lane = threadIdx.x & 31;
    int n    = lane & 15;
    int pair = wg >> 3;
    int c    = wg & (CHUNKS - 1);
    if (pair >= BSZ * D_INNER / 2) return;
    int q  = pair * 2 + (lane >> 4);
    int b  = q >> 11;
    int d  = q & (D_INNER - 1);

    const float An  = -expf(A_log[d * D_STATE + n]);
    const float dtw = dt_w[d];
    const float dtb = dt_b[d];
    const float Dd  = Dp[d];

    float h = H[((size_t)((b * CHUNKS + c) * D_INNER) + d) * D_STATE + n];

    const int t0 = c * CHUNK_T;
    const float* pr0 = proj + (size_t)(b * LEN + t0) * NPROJ;
    const float* xc0 = xc + (size_t)(b * LEN + t0) * D_INNER + d;
    const float* z0  = xz + (size_t)(b * LEN + t0) * (2 * D_INNER) + D_INNER + d;
    float*       Y0  = Y  + (size_t)(b * LEN + t0) * D_INNER + d;

    #pragma unroll 2
    for (int t = 0; t < CHUNK_T; t++) {
        const float* pr = pr0 + (size_t)t * NPROJ;
        float dtraw = pr[0];
        float Bn    = pr[1 + n];
        float Cn    = pr[1 + D_STATE + n];
        float xcv   = xc0[(size_t)t * D_INNER];
        float zv    = z0 [(size_t)t * (2 * D_INNER)];

        float s  = fmaf(dtraw, dtw, dtb);
        float dt = (s > 20.f) ? s : log1pf(__expf(s));
        float dA = __expf(dt * An);
        h = fmaf(dA, h, dt * Bn * xcv);

        float yp = h * Cn;
        yp += __shfl_xor_sync(0xffffffffu, yp, 8);
        yp += __shfl_xor_sync(0xffffffffu, yp, 4);
        yp += __shfl_xor_sync(0xffffffffu, yp, 2);
        yp += __shfl_xor_sync(0xffffffffu, yp, 1);

        if (n == 0) {
            float sig = 1.f / (1.f + __expf(-zv));
            Y0[(size_t)t * D_INNER] = (yp + xcv * Dd) * (zv * sig);
        }
    }
}

// ---------------- launch -----------------------------------------------------
extern "C" void kernel_launch(void* const* d_in, const int* in_sizes, int n_in,
                              void* d_out, int out_size)
{
    const float* x      = (const float*)d_in[0];
    const float* W_in   = (const float*)d_in[1];
    const float* conv_w = (const float*)d_in[2];
    const float* conv_b = (const float*)d_in[3];
    const float* W_x    = (const float*)d_in[4];
    const float* dt_w   = (const float*)d_in[5];
    const float* dt_b   = (const float*)d_in[6];
    const float* A_log  = (const float*)d_in[7];
    const float* D_par  = (const float*)d_in[8];
    const float* W_out  = (const float*)d_in[9];
    float* out = (float*)d_out;

    float *xz, *xc, *proj, *Y, *P, *Qc, *H;
    cudaGetSymbolAddress((void**)&xz,   g_xz);
    cudaGetSymbolAddress((void**)&xc,   g_xc);
    cudaGetSymbolAddress((void**)&proj, g_proj);
    cudaGetSymbolAddress((void**)&Y,    g_Y);
    cudaGetSymbolAddress((void**)&P,    g_P);
    cudaGetSymbolAddress((void**)&Qc,   g_Qc);
    cudaGetSymbolAddress((void**)&H,    g_H);

    // 1) xz = x @ W_in^T : M=2048, N=4096, K=1024
    {
        dim3 grid(2 * D_INNER / 128, M_TOT / 128);
        sgemm_nt<<<grid, 256>>>(x, W_in, xz, M_TOT, 2 * D_INNER, D_MODEL);
    }
    // 2) conv + silu
    {
        int total = M_TOT * D_INNER;
        conv_silu_kernel<<<(total + 255) / 256, 256>>>(xz, conv_w, conv_b, xc);
    }
    // 3) proj = xc @ W_x^T
    {
        xproj_kernel<<<M_TOT / 8, 256>>>(xc, W_x, proj);
    }
    // 4) chunked selective scan + gating -> Y
    {
        int nwarp = (BSZ * D_INNER / 2) * CHUNKS;     // 16384 warps
        scan_pass1<<<nwarp / 8, 256>>>(proj, xc, dt_w, dt_b, A_log, P, Qc);
        scan_pass2<<<(BSZ * D_INNER * D_STATE) / 256, 256>>>(P, Qc, H);
        scan_pass3<<<nwarp / 8, 256>>>(proj, xc, xz, dt_w, dt_b, A_log, D_par,
                                       H, Y);
    }
    // 5) out = Y @ W_out^T : M=2048, N=1024, K=2048
    {
        dim3 grid(D_MODEL / 128, M_TOT / 128);
        sgemm_nt<<<grid, 256>>>(Y, W_out, out, M_TOT, D_MODEL, D_INNER);
    }
}

// round 4
// speedup vs baseline: 1.7615x; 1.5224x over previous
#include <cuda_runtime.h>
#include <cuda_bf16.h>
#include <math.h>
#include <stdint.h>

#define D_MODEL 1024
#define D_STATE 16
#define D_INNER 2048
#define BSZ     2
#define LEN     1024
#define M_TOT   (BSZ*LEN)
#define NPROJ   (2*D_STATE+1)
#define CHUNKS  8
#define CHUNK_T (LEN/CHUNKS)

// ---------------- scratch --------------------------------------------------
__device__ float g_xz[(size_t)M_TOT * 2 * D_INNER];
__device__ float g_xc[(size_t)M_TOT * D_INNER];
__device__ float g_proj[(size_t)M_TOT * NPROJ];
__device__ float g_P [(size_t)BSZ * CHUNKS * D_INNER * D_STATE];
__device__ float g_Qc[(size_t)BSZ * CHUNKS * D_INNER * D_STATE];
__device__ float g_H [(size_t)BSZ * CHUNKS * D_INNER * D_STATE];
// bf16 hi/lo splits
__device__ __nv_bfloat16 g_xhi[(size_t)M_TOT * D_MODEL];
__device__ __nv_bfloat16 g_xlo[(size_t)M_TOT * D_MODEL];
__device__ __nv_bfloat16 g_w1hi[(size_t)2 * D_INNER * D_MODEL];
__device__ __nv_bfloat16 g_w1lo[(size_t)2 * D_INNER * D_MODEL];
__device__ __nv_bfloat16 g_w2hi[(size_t)D_MODEL * D_INNER];
__device__ __nv_bfloat16 g_w2lo[(size_t)D_MODEL * D_INNER];
__device__ __nv_bfloat16 g_yhi[(size_t)M_TOT * D_INNER];
__device__ __nv_bfloat16 g_ylo[(size_t)M_TOT * D_INNER];

// ---------------- helpers ----------------------------------------------------
__device__ __forceinline__ uint32_t smem_u32(const void* p) {
    uint32_t a;
    asm("{ .reg .u64 t; cvta.to.shared.u64 t, %1; cvt.u32.u64 %0, t; }"
        : "=r"(a) : "l"(p));
    return a;
}
__device__ __forceinline__ uint32_t sw128(uint32_t off) {
    return off ^ ((off >> 3) & 0x70);
}
__device__ __forceinline__ uint32_t pack_bf2(float f0, float f1) {
    uint32_t r;
    asm("cvt.rn.bf16x2.f32 %0, %1, %2;" : "=r"(r) : "f"(f1), "f"(f0));
    return r;
}
__device__ __forceinline__ void ldsm4(uint32_t* r, uint32_t addr) {
    asm volatile("ldmatrix.sync.aligned.m8n8.x4.shared.b16 {%0,%1,%2,%3}, [%4];"
        : "=r"(r[0]), "=r"(r[1]), "=r"(r[2]), "=r"(r[3]) : "r"(addr));
}
__device__ __forceinline__ void mma_bf16(float* d, const uint32_t* a,
                                         const uint32_t* b) {
    asm volatile(
        "mma.sync.aligned.m16n8k16.row.col.f32.bf16.bf16.f32 "
        "{%0,%1,%2,%3}, {%4,%5,%6,%7}, {%8,%9}, {%0,%1,%2,%3};"
        : "+f"(d[0]), "+f"(d[1]), "+f"(d[2]), "+f"(d[3])
        : "r"(a[0]), "r"(a[1]), "r"(a[2]), "r"(a[3]), "r"(b[0]), "r"(b[1]));
}

// ---------------- hi/lo split ------------------------------------------------
__global__ void split_kernel(const float* __restrict__ in,
                             __nv_bfloat16* __restrict__ hi,
                             __nv_bfloat16* __restrict__ lo, int n4)
{
    int i = blockIdx.x * blockDim.x + threadIdx.x;
    if (i >= n4) return;
    float4 v = ((const float4*)in)[i];
    float hx = __bfloat162float(__float2bfloat16(v.x));
    float hy = __bfloat162float(__float2bfloat16(v.y));
    float hz = __bfloat162float(__float2bfloat16(v.z));
    float hw = __bfloat162float(__float2bfloat16(v.w));
    uint2 h, l;
    h.x = pack_bf2(v.x, v.y);  h.y = pack_bf2(v.z, v.w);
    l.x = pack_bf2(v.x - hx, v.y - hy);
    l.y = pack_bf2(v.z - hz, v.w - hw);
    ((uint2*)hi)[i] = h;
    ((uint2*)lo)[i] = l;
}

// ---------------- mma.sync GEMM (NT): C[M,N] = A[M,K] @ B[N,K]^T --------------
// bf16 hi/lo inputs: C(fp32) = Ahi*Bhi + Ahi*Blo + Alo*Bhi (fp32 accum in MMA).
// 128x128 tile, K-chunk 64 (SW128 row = 64 bf16 = 128B), 8 warps, 32x64/warp.
#define OFF_AHI 0
#define OFF_ALO 16384
#define OFF_BHI 32768
#define OFF_BLO 49152
#define GEMM_SMEM (1024 + 4*16384)

__global__ void __launch_bounds__(256)
mma_gemm_nt(const __nv_bfloat16* __restrict__ Ahi, const __nv_bfloat16* __restrict__ Alo,
            const __nv_bfloat16* __restrict__ Bhi, const __nv_bfloat16* __restrict__ Blo,
            float* __restrict__ C, int M, int N, int K)
{
    extern __shared__ char smc[];
    const uint32_t smb0 = smem_u32(smc);
    const uint32_t smb  = (smb0 + 1023) & ~1023u;   // 1024-align for swizzle
    char* smp = smc + (smb - smb0);

    const int tid = threadIdx.x, wid = tid >> 5, lane = tid & 31;
    const int row0 = blockIdx.y * 128, col0 = blockIdx.x * 128;
    const int wm = (wid & 3) * 32;       // warp row within tile
    const int wn = (wid >> 2) * 64;      // warp col within tile

    float acc[2][8][4];
    #pragma unroll
    for (int a = 0; a < 2; a++)
        #pragma unroll
        for (int b = 0; b < 8; b++)
            #pragma unroll
            for (int c = 0; c < 4; c++) acc[a][b][c] = 0.f;

    // per-lane ldmatrix address components
    const int lj = lane >> 3;     // matrix index 0..3
    const int lr = lane & 7;      // row within 8x8 matrix

    const int nchunk = K >> 6;
    for (int kc = 0; kc < nchunk; kc++) {
        const __nv_bfloat16* pAh = Ahi + (size_t)row0 * K + kc * 64;
        const __nv_bfloat16* pAl = Alo + (size_t)row0 * K + kc * 64;
        const __nv_bfloat16* pBh = Bhi + (size_t)col0 * K + kc * 64;
        const __nv_bfloat16* pBl = Blo + (size_t)col0 * K + kc * 64;

        #pragma unroll
        for (int i = 0; i < 4; i++) {
            int ch = tid + 256 * i;           // 0..1023 16B-chunks
            int r = ch >> 3, c = ch & 7;
            uint32_t so = sw128((uint32_t)(r * 128 + c * 16));
            size_t g = (size_t)r * K + c * 8;
            *(uint4*)(smp + OFF_AHI + so) = *(const uint4*)(pAh + g);
            *(uint4*)(smp + OFF_ALO + so) = *(const uint4*)(pAl + g);
            *(uint4*)(smp + OFF_BHI + so) = *(const uint4*)(pBh + g);
            *(uint4*)(smp + OFF_BLO + so) = *(const uint4*)(pBl + g);
        }
        __syncthreads();

        #pragma unroll
        for (int ks = 0; ks < 4; ks++) {
            // A frags: matrix j -> m-half = j&1, k-half = j>>1
            uint32_t ah[2][4], al[2][4];
            #pragma unroll
            for (int mt = 0; mt < 2; mt++) {
                int rr = wm + mt * 16 + (lj & 1) * 8 + lr;
                int kb = ks * 32 + (lj >> 1) * 16;
                uint32_t so = sw128((uint32_t)(rr * 128 + kb));
                ldsm4(ah[mt], smb + OFF_AHI + so);
                ldsm4(al[mt], smb + OFF_ALO + so);
            }
            // B frags: matrix j -> n-half = j>>1, k-half = j&1
            uint32_t bh[4][4], bl[4][4];
            #pragma unroll
            for (int np = 0; np < 4; np++) {
                int rr = wn + np * 16 + (lj >> 1) * 8 + lr;
                int kb = ks * 32 + (lj & 1) * 16;
                uint32_t so = sw128((uint32_t)(rr * 128 + kb));
                ldsm4(bh[np], smb + OFF_BHI + so);
                ldsm4(bl[np], smb + OFF_BLO + so);
            }
            #pragma unroll
            for (int mt = 0; mt < 2; mt++) {
                #pragma unroll
                for (int np = 0; np < 4; np++) {
                    mma_bf16(acc[mt][2*np+0], ah[mt], &bh[np][0]);
                    mma_bf16(acc[mt][2*np+0], ah[mt], &bl[np][0]);
                    mma_bf16(acc[mt][2*np+0], al[mt], &bh[np][0]);
                    mma_bf16(acc[mt][2*np+1], ah[mt], &bh[np][2]);
                    mma_bf16(acc[mt][2*np+1], ah[mt], &bl[np][2]);
                    mma_bf16(acc[mt][2*np+1], al[mt], &bh[np][2]);
                }
            }
        }
        __syncthreads();
    }

    // epilogue: d0,d1 -> (row, col..col+1), d2,d3 -> (row+8, same)
    #pragma unroll
    for (int mt = 0; mt < 2; mt++) {
        int row = row0 + wm + mt * 16 + (lane >> 2);
        #pragma unroll
        for (int nt = 0; nt < 8; nt++) {
            int col = col0 + wn + nt * 8 + 2 * (lane & 3);
            float2 v0 = make_float2(acc[mt][nt][0], acc[mt][nt][1]);
            float2 v1 = make_float2(acc[mt][nt][2], acc[mt][nt][3]);
            *(float2*)(C + (size_t)row * N + col) = v0;
            *(float2*)(C + (size_t)(row + 8) * N + col) = v1;
        }
    }
}

// ---------------- causal depthwise conv (K=4) + SiLU ------------------------
__global__ void conv_silu_kernel(const float* __restrict__ xz,
                                 const float* __restrict__ cw,
                                 const float* __restrict__ cb,
                                 float* __restrict__ xc)
{
    int idx = blockIdx.x * blockDim.x + threadIdx.x;
    if (idx >= M_TOT * D_INNER) return;
    int d = idx & (D_INNER - 1);
    int m = idx >> 11;
    int l = m & (LEN - 1);

    const float w0 = cw[d * 4 + 0], w1 = cw[d * 4 + 1];
    const float w2 = cw[d * 4 + 2], w3 = cw[d * 4 + 3];
    const float* base = xz + (size_t)m * (2 * D_INNER) + d;
    const int stride = 2 * D_INNER;

    float acc = cb[d] + w3 * base[0];
    if (l >= 1) acc += w2 * base[-stride];
    if (l >= 2) acc += w1 * base[-2 * stride];
    if (l >= 3) acc += w0 * base[-3 * stride];

    float sig = 1.f / (1.f + __expf(-acc));
    xc[idx] = acc * sig;
}

// ---------------- x-proj -----------------------------------------------------
__global__ void __launch_bounds__(256)
xproj_kernel(const float* __restrict__ xc, const float* __restrict__ Wx,
             float* __restrict__ proj)
{
    int warp = (blockIdx.x * blockDim.x + threadIdx.x) >> 5;
    int lane = threadIdx.x & 31;
    if (warp >= M_TOT) return;

    const float* xr = xc + (size_t)warp * D_INNER;
    float acc[NPROJ];
    #pragma unroll
    for (int e = 0; e < NPROJ; e++) acc[e] = 0.f;

    for (int k = lane; k < D_INNER; k += 32) {
        float xv = xr[k];
        #pragma unroll
        for (int e = 0; e < NPROJ; e++)
            acc[e] = fmaf(xv, Wx[(size_t)e * D_INNER + k], acc[e]);
    }
    #pragma unroll
    for (int e = 0; e < NPROJ; e++) {
        float v = acc[e];
        v += __shfl_xor_sync(0xffffffffu, v, 16);
        v += __shfl_xor_sync(0xffffffffu, v, 8);
        v += __shfl_xor_sync(0xffffffffu, v, 4);
        v += __shfl_xor_sync(0xffffffffu, v, 2);
        v += __shfl_xor_sync(0xffffffffu, v, 1);
        if (lane == (e & 31)) proj[(size_t)warp * NPROJ + e] = v;
    }
}

// ---------------- chunked selective scan -------------------------------------
__global__ void __launch_bounds__(256)
scan_pass1(const float* __restrict__ proj, const float* __restrict__ xc,
           const float* __restrict__ dt_w, const float* __restrict__ dt_b,
           const float* __restrict__ A_log,
           float* __restrict__ P, float* __restrict__ Q)
{
    int wg   = (blockIdx.x * blockDim.x + threadIdx.x) >> 5;
    int lane = threadIdx.x & 31;
    int n    = lane & 15;
    int pair = wg >> 3;
    int c    = wg & (CHUNKS - 1);
    if (pair >= BSZ * D_INNER / 2) return;
    int q  = pair * 2 + (lane >> 4);
    int b  = q >> 11;
    int d  = q & (D_INNER - 1);

    const float An  = -expf(A_log[d * D_STATE + n]);
    const float dtw = dt_w[d];
    const float dtb = dt_b[d];

    float Pp = 1.f, acc = 0.f;
    const int t0 = c * CHUNK_T;
    const float* pr0 = proj + (size_t)(b * LEN + t0) * NPROJ;
    const float* xc0 = xc + (size_t)(b * LEN + t0) * D_INNER + d;

    #pragma unroll 2
    for (int t = 0; t < CHUNK_T; t++) {
        const float* pr = pr0 + (size_t)t * NPROJ;
        float dtraw = pr[0];
        float Bn    = pr[1 + n];
        float xcv   = xc0[(size_t)t * D_INNER];

        float s  = fmaf(dtraw, dtw, dtb);
        float dt = (s > 20.f) ? s : log1pf(__expf(s));
        float dA = __expf(dt * An);
        acc = fmaf(dA, acc, dt * Bn * xcv);
        Pp *= dA;
    }
    size_t o = ((size_t)((b * CHUNKS + c) * D_INNER) + d) * D_STATE + n;
    P[o] = Pp;
    Q[o] = acc;
}

__global__ void __launch_bounds__(256)
scan_pass2(const float* __restrict__ P, const float* __restrict__ Q,
           float* __restrict__ H)
{
    int i = blockIdx.x * blockDim.x + threadIdx.x;
    if (i >= BSZ * D_INNER * D_STATE) return;
    int n = i & 15;
    int d = (i >> 4) & (D_INNER - 1);
    int b = i >> 15;

    float h = 0.f;
    #pragma unroll
    for (int c = 0; c < CHUNKS; c++) {
        size_t o = ((size_t)((b * CHUNKS + c) * D_INNER) + d) * D_STATE + n;
        H[o] = h;
        h = fmaf(P[o], h, Q[o]);
    }
}

__global__ void __launch_bounds__(256)
scan_pass3(const float* __restrict__ proj, const float* __restrict__ xc,
           const float* __restrict__ xz,
           const float* __restrict__ dt_w, const float* __restrict__ dt_b,
           const float* __restrict__ A_log, const float* __restrict__ Dp,
           const float* __restrict__ H,
           __nv_bfloat16* __restrict__ Yhi, __nv_bfloat16* __restrict__ Ylo)
{
    int wg   = (blockIdx.x * blockDim.x + threadIdx.x) >> 5;
    int lane = threadIdx.x & 31;
    int n    = lane & 15;
    int pair = wg >> 3;
    int c    = wg & (CHUNKS - 1);
    if (pair >= BSZ * D_INNER / 2) return;
    int q  = pair * 2 + (lane >> 4);
    int b  = q >> 11;
    int d  = q & (D_INNER - 1);

    const float An  = -expf(A_log[d * D_STATE + n]);
    const float dtw = dt_w[d];
    const float dtb = dt_b[d];
    const float Dd  = Dp[d];

    float h = H[((size_t)((b * CHUNKS + c) * D_INNER) + d) * D_STATE + n];

    const int t0 = c * CHUNK_T;
    const float* pr0 = proj + (size_t)(b * LEN + t0) * NPROJ;
    const float* xc0 = xc + (size_t)(b * LEN + t0) * D_INNER + d;
    const float* z0  = xz + (size_t)(b * LEN + t0) * (2 * D_INNER) + D_INNER + d;
    __nv_bfloat16* Yh0 = Yhi + (size_t)(b * LEN + t0) * D_INNER + d;
    __nv_bfloat16* Yl0 = Ylo + (size_t)(b * LEN + t0) * D_INNER + d;

    #pragma unroll 2
    for (int t = 0; t < CHUNK_T; t++) {
        const float* pr = pr0 + (size_t)t * NPROJ;
        float dtraw = pr[0];
        float Bn    = pr[1 + n];
        float Cn    = pr[1 + D_STATE + n];
        float xcv   = xc0[(size_t)t * D_INNER];
        float zv    = z0 [(size_t)t * (2 * D_INNER)];

        float s  = fmaf(dtraw, dtw, dtb);
        float dt = (s > 20.f) ? s : log1pf(__expf(s));
        float dA = __expf(dt * An);
        h = fmaf(dA, h, dt * Bn * xcv);

        float yp = h * Cn;
        yp += __shfl_xor_sync(0xffffffffu, yp, 8);
        yp += __shfl_xor_sync(0xffffffffu, yp, 4);
        yp += __shfl_xor_sync(0xffffffffu, yp, 2);
        yp += __shfl_xor_sync(0xffffffffu, yp, 1);

        if (n == 0) {
            float sig = 1.f / (1.f + __expf(-zv));
            float yv = (yp + xcv * Dd) * (zv * sig);
            __nv_bfloat16 hv = __float2bfloat16(yv);
            Yh0[(size_t)t * D_INNER] = hv;
            Yl0[(size_t)t * D_INNER] = __float2bfloat16(yv - __bfloat162float(hv));
        }
    }
}

// ---------------- launch -----------------------------------------------------
extern "C" void kernel_launch(void* const* d_in, const int* in_sizes, int n_in,
                              void* d_out, int out_size)
{
    const float* x      = (const float*)d_in[0];
    const float* W_in   = (const float*)d_in[1];
    const float* conv_w = (const float*)d_in[2];
    const float* conv_b = (const float*)d_in[3];
    const float* W_x    = (const float*)d_in[4];
    const float* dt_w   = (const float*)d_in[5];
    const float* dt_b   = (const float*)d_in[6];
    const float* A_log  = (const float*)d_in[7];
    const float* D_par  = (const float*)d_in[8];
    const float* W_out  = (const float*)d_in[9];
    float* out = (float*)d_out;

    float *xz, *xc, *proj, *P, *Qc, *H;
    __nv_bfloat16 *xhi, *xlo, *w1hi, *w1lo, *w2hi, *w2lo, *yhi, *ylo;
    cudaGetSymbolAddress((void**)&xz,   g_xz);
    cudaGetSymbolAddress((void**)&xc,   g_xc);
    cudaGetSymbolAddress((void**)&proj, g_proj);
    cudaGetSymbolAddress((void**)&P,    g_P);
    cudaGetSymbolAddress((void**)&Qc,   g_Qc);
    cudaGetSymbolAddress((void**)&H,    g_H);
    cudaGetSymbolAddress((void**)&xhi,  g_xhi);
    cudaGetSymbolAddress((void**)&xlo,  g_xlo);
    cudaGetSymbolAddress((void**)&w1hi, g_w1hi);
    cudaGetSymbolAddress((void**)&w1lo, g_w1lo);
    cudaGetSymbolAddress((void**)&w2hi, g_w2hi);
    cudaGetSymbolAddress((void**)&w2lo, g_w2lo);
    cudaGetSymbolAddress((void**)&yhi,  g_yhi);
    cudaGetSymbolAddress((void**)&ylo,  g_ylo);

    cudaFuncSetAttribute(mma_gemm_nt, cudaFuncAttributeMaxDynamicSharedMemorySize,
                         GEMM_SMEM);

    // 0) hi/lo splits of x, W_in, W_out
    {
        int n4;
        n4 = (M_TOT * D_MODEL) / 4;
        split_kernel<<<(n4 + 255) / 256, 256>>>(x, xhi, xlo, n4);
        n4 = (2 * D_INNER * D_MODEL) / 4;
        split_kernel<<<(n4 + 255) / 256, 256>>>(W_in, w1hi, w1lo, n4);
        n4 = (D_MODEL * D_INNER) / 4;
        split_kernel<<<(n4 + 255) / 256, 256>>>(W_out, w2hi, w2lo, n4);
    }
    // 1) xz = x @ W_in^T : M=2048, N=4096, K=1024 (mma.sync bf16 hi/lo)
    {
        dim3 grid(2 * D_INNER / 128, M_TOT / 128);
        mma_gemm_nt<<<grid, 256, GEMM_SMEM>>>(xhi, xlo, w1hi, w1lo, xz,
                                              M_TOT, 2 * D_INNER, D_MODEL);
    }
    // 2) conv + silu
    {
        int total = M_TOT * D_INNER;
        conv_silu_kernel<<<(total + 255) / 256, 256>>>(xz, conv_w, conv_b, xc);
    }
    // 3) proj = xc @ W_x^T
    {
        xproj_kernel<<<M_TOT / 8, 256>>>(xc, W_x, proj);
    }
    // 4) chunked selective scan + gating -> Y (bf16 hi/lo)
    {
        int nwarp = (BSZ * D_INNER / 2) * CHUNKS;
        scan_pass1<<<nwarp / 8, 256>>>(proj, xc, dt_w, dt_b, A_log, P, Qc);
        scan_pass2<<<(BSZ * D_INNER * D_STATE) / 256, 256>>>(P, Qc, H);
        scan_pass3<<<nwarp / 8, 256>>>(proj, xc, xz, dt_w, dt_b, A_log, D_par,
                                       H, yhi, ylo);
    }
    // 5) out = Y @ W_out^T : M=2048, N=1024, K=2048 (mma.sync bf16 hi/lo)
    {
        dim3 grid(D_MODEL / 128, M_TOT / 128);
        mma_gemm_nt<<<grid, 256, GEMM_SMEM>>>(yhi, ylo, w2hi, w2lo, out,
                                              M_TOT, D_MODEL, D_INNER);
    }
}

// round 5
// speedup vs baseline: 2.6904x; 1.5274x over previous
#include <cuda_runtime.h>
#include <cuda_bf16.h>
#include <math.h>
#include <stdint.h>

#define D_MODEL 1024
#define D_STATE 16
#define D_INNER 2048
#define BSZ     2
#define LEN     1024
#define M_TOT   (BSZ*LEN)
#define NPROJ   (2*D_STATE+1)
#define CHUNKS  8
#define CHUNK_T (LEN/CHUNKS)

// ---------------- scratch --------------------------------------------------
__device__ float g_xz[(size_t)M_TOT * 2 * D_INNER];
__device__ float g_xc[(size_t)M_TOT * D_INNER];
__device__ float g_proj[(size_t)M_TOT * NPROJ];
__device__ float g_dt[(size_t)M_TOT * D_INNER];
__device__ float g_P [(size_t)BSZ * CHUNKS * D_INNER * D_STATE];
__device__ float g_Qc[(size_t)BSZ * CHUNKS * D_INNER * D_STATE];
__device__ float g_H [(size_t)BSZ * CHUNKS * D_INNER * D_STATE];
__device__ __nv_bfloat16 g_xhi[(size_t)M_TOT * D_MODEL];
__device__ __nv_bfloat16 g_xlo[(size_t)M_TOT * D_MODEL];
__device__ __nv_bfloat16 g_w1hi[(size_t)2 * D_INNER * D_MODEL];
__device__ __nv_bfloat16 g_w1lo[(size_t)2 * D_INNER * D_MODEL];
__device__ __nv_bfloat16 g_w2hi[(size_t)D_MODEL * D_INNER];
__device__ __nv_bfloat16 g_w2lo[(size_t)D_MODEL * D_INNER];
__device__ __nv_bfloat16 g_yhi[(size_t)M_TOT * D_INNER];
__device__ __nv_bfloat16 g_ylo[(size_t)M_TOT * D_INNER];

// ---------------- helpers ----------------------------------------------------
__device__ __forceinline__ uint32_t smem_u32(const void* p) {
    uint32_t a;
    asm("{ .reg .u64 t; cvta.to.shared.u64 t, %1; cvt.u32.u64 %0, t; }"
        : "=r"(a) : "l"(p));
    return a;
}
__device__ __forceinline__ uint32_t sw128(uint32_t off) {
    return off ^ ((off >> 3) & 0x70);
}
__device__ __forceinline__ uint32_t pack_bf2(float f0, float f1) {
    uint32_t r;
    asm("cvt.rn.bf16x2.f32 %0, %1, %2;" : "=r"(r) : "f"(f1), "f"(f0));
    return r;
}
__device__ __forceinline__ void ldsm4(uint32_t* r, uint32_t addr) {
    asm volatile("ldmatrix.sync.aligned.m8n8.x4.shared.b16 {%0,%1,%2,%3}, [%4];"
        : "=r"(r[0]), "=r"(r[1]), "=r"(r[2]), "=r"(r[3]) : "r"(addr));
}
__device__ __forceinline__ void mma_bf16(float* d, const uint32_t* a,
                                         const uint32_t* b) {
    asm volatile(
        "mma.sync.aligned.m16n8k16.row.col.f32.bf16.bf16.f32 "
        "{%0,%1,%2,%3}, {%4,%5,%6,%7}, {%8,%9}, {%0,%1,%2,%3};"
        : "+f"(d[0]), "+f"(d[1]), "+f"(d[2]), "+f"(d[3])
        : "r"(a[0]), "r"(a[1]), "r"(a[2]), "r"(a[3]), "r"(b[0]), "r"(b[1]));
}
__device__ __forceinline__ void cp16(uint32_t dst, const void* src) {
    asm volatile("cp.async.cg.shared.global [%0], [%1], 16;"
                 :: "r"(dst), "l"(src));
}

// ---------------- hi/lo split ------------------------------------------------
__global__ void split_kernel(const float* __restrict__ in,
                             __nv_bfloat16* __restrict__ hi,
                             __nv_bfloat16* __restrict__ lo, int n4)
{
    int i = blockIdx.x * blockDim.x + threadIdx.x;
    if (i >= n4) return;
    float4 v = ((const float4*)in)[i];
    float hx = __bfloat162float(__float2bfloat16(v.x));
    float hy = __bfloat162float(__float2bfloat16(v.y));
    float hz = __bfloat162float(__float2bfloat16(v.z));
    float hw = __bfloat162float(__float2bfloat16(v.w));
    uint2 h, l;
    h.x = pack_bf2(v.x, v.y);  h.y = pack_bf2(v.z, v.w);
    l.x = pack_bf2(v.x - hx, v.y - hy);
    l.y = pack_bf2(v.z - hz, v.w - hw);
    ((uint2*)hi)[i] = h;
    ((uint2*)lo)[i] = l;
}

// ---------------- mma.sync GEMM (NT), 3-stage cp.async pipeline ---------------
// C[M,N] = Ahi*Bhi + Ahi*Blo + Alo*Bhi (fp32 accum). 128x128 tile, K-chunk 64.
#define OFF_AHI 0
#define OFF_ALO 16384
#define OFF_BHI 32768
#define OFF_BLO 49152
#define STAGE_BYTES 65536
#define STAGES 3
#define GEMM_SMEM (1024 + STAGES*STAGE_BYTES)

__global__ void __launch_bounds__(256)
mma_gemm_nt(const __nv_bfloat16* __restrict__ Ahi, const __nv_bfloat16* __restrict__ Alo,
            const __nv_bfloat16* __restrict__ Bhi, const __nv_bfloat16* __restrict__ Blo,
            float* __restrict__ C, int M, int N, int K)
{
    extern __shared__ char smc[];
    const uint32_t smb0 = smem_u32(smc);
    const uint32_t smb  = (smb0 + 1023) & ~1023u;

    const int tid = threadIdx.x, wid = tid >> 5, lane = tid & 31;
    const int row0 = blockIdx.y * 128, col0 = blockIdx.x * 128;
    const int wm = (wid & 3) * 32;
    const int wn = (wid >> 2) * 64;

    float acc[2][8][4];
    #pragma unroll
    for (int a = 0; a < 2; a++)
        #pragma unroll
        for (int b = 0; b < 8; b++)
            #pragma unroll
            for (int c = 0; c < 4; c++) acc[a][b][c] = 0.f;

    const int lj = lane >> 3;
    const int lr = lane & 7;
    const int nchunk = K >> 6;

    // per-thread source/dest components for copies (4 x 16B per array per chunk)
    auto load_chunk = [&](int kc, int stage) {
        const __nv_bfloat16* pAh = Ahi + (size_t)row0 * K + kc * 64;
        const __nv_bfloat16* pAl = Alo + (size_t)row0 * K + kc * 64;
        const __nv_bfloat16* pBh = Bhi + (size_t)col0 * K + kc * 64;
        const __nv_bfloat16* pBl = Blo + (size_t)col0 * K + kc * 64;
        uint32_t sb = smb + stage * STAGE_BYTES;
        #pragma unroll
        for (int i = 0; i < 4; i++) {
            int ch = tid + 256 * i;
            int r = ch >> 3, c = ch & 7;
            uint32_t so = sw128((uint32_t)(r * 128 + c * 16));
            size_t g = (size_t)r * K + c * 8;
            cp16(sb + OFF_AHI + so, pAh + g);
            cp16(sb + OFF_ALO + so, pAl + g);
            cp16(sb + OFF_BHI + so, pBh + g);
            cp16(sb + OFF_BLO + so, pBl + g);
        }
        asm volatile("cp.async.commit_group;" ::: "memory");
    };

    // prologue: stages 0..STAGES-2
    load_chunk(0, 0);
    if (nchunk > 1) load_chunk(1, 1);

    for (int kc = 0; kc < nchunk; kc++) {
        asm volatile("cp.async.wait_group %0;" :: "n"(STAGES - 2) : "memory");
        __syncthreads();
        if (kc + STAGES - 1 < nchunk)
            load_chunk(kc + STAGES - 1, (kc + STAGES - 1) % STAGES);

        uint32_t sb = smb + (kc % STAGES) * STAGE_BYTES;
        #pragma unroll
        for (int ks = 0; ks < 4; ks++) {
            uint32_t ah[2][4], al[2][4];
            #pragma unroll
            for (int mt = 0; mt < 2; mt++) {
                int rr = wm + mt * 16 + (lj & 1) * 8 + lr;
                int kb = ks * 32 + (lj >> 1) * 16;
                uint32_t so = sw128((uint32_t)(rr * 128 + kb));
                ldsm4(ah[mt], sb + OFF_AHI + so);
                ldsm4(al[mt], sb + OFF_ALO + so);
            }
            uint32_t bh[4][4], bl[4][4];
            #pragma unroll
            for (int np = 0; np < 4; np++) {
                int rr = wn + np * 16 + (lj >> 1) * 8 + lr;
                int kb = ks * 32 + (lj & 1) * 16;
                uint32_t so = sw128((uint32_t)(rr * 128 + kb));
                ldsm4(bh[np], sb + OFF_BHI + so);
                ldsm4(bl[np], sb + OFF_BLO + so);
            }
            #pragma unroll
            for (int mt = 0; mt < 2; mt++) {
                #pragma unroll
                for (int np = 0; np < 4; np++) {
                    mma_bf16(acc[mt][2*np+0], ah[mt], &bh[np][0]);
                    mma_bf16(acc[mt][2*np+0], ah[mt], &bl[np][0]);
                    mma_bf16(acc[mt][2*np+0], al[mt], &bh[np][0]);
                    mma_bf16(acc[mt][2*np+1], ah[mt], &bh[np][2]);
                    mma_bf16(acc[mt][2*np+1], ah[mt], &bl[np][2]);
                    mma_bf16(acc[mt][2*np+1], al[mt], &bh[np][2]);
                }
            }
        }
    }

    #pragma unroll
    for (int mt = 0; mt < 2; mt++) {
        int row = row0 + wm + mt * 16 + (lane >> 2);
        #pragma unroll
        for (int nt = 0; nt < 8; nt++) {
            int col = col0 + wn + nt * 8 + 2 * (lane & 3);
            float2 v0 = make_float2(acc[mt][nt][0], acc[mt][nt][1]);
            float2 v1 = make_float2(acc[mt][nt][2], acc[mt][nt][3]);
            *(float2*)(C + (size_t)row * N + col) = v0;
            *(float2*)(C + (size_t)(row + 8) * N + col) = v1;
        }
    }
}

// ---------------- causal depthwise conv (K=4) + SiLU ------------------------
__global__ void conv_silu_kernel(const float* __restrict__ xz,
                                 const float* __restrict__ cw,
                                 const float* __restrict__ cb,
                                 float* __restrict__ xc)
{
    int idx = blockIdx.x * blockDim.x + threadIdx.x;
    if (idx >= M_TOT * D_INNER) return;
    int d = idx & (D_INNER - 1);
    int m = idx >> 11;
    int l = m & (LEN - 1);

    const float w0 = cw[d * 4 + 0], w1 = cw[d * 4 + 1];
    const float w2 = cw[d * 4 + 2], w3 = cw[d * 4 + 3];
    const float* base = xz + (size_t)m * (2 * D_INNER) + d;
    const int stride = 2 * D_INNER;

    float acc = cb[d] + w3 * base[0];
    if (l >= 1) acc += w2 * base[-stride];
    if (l >= 2) acc += w1 * base[-2 * stride];
    if (l >= 3) acc += w0 * base[-3 * stride];

    float sig = 1.f / (1.f + __expf(-acc));
    xc[idx] = acc * sig;
}

// ---------------- x-proj (float4 vectorized) ---------------------------------
__global__ void __launch_bounds__(256)
xproj_kernel(const float* __restrict__ xc, const float* __restrict__ Wx,
             float* __restrict__ proj)
{
    int warp = (blockIdx.x * blockDim.x + threadIdx.x) >> 5;
    int lane = threadIdx.x & 31;
    if (warp >= M_TOT) return;

    const float4* xr = (const float4*)(xc + (size_t)warp * D_INNER);
    float acc[NPROJ];
    #pragma unroll
    for (int e = 0; e < NPROJ; e++) acc[e] = 0.f;

    for (int k4 = lane; k4 < D_INNER / 4; k4 += 32) {
        float4 xv = xr[k4];
        #pragma unroll
        for (int e = 0; e < NPROJ; e++) {
            float4 wv = ((const float4*)(Wx + (size_t)e * D_INNER))[k4];
            float s = fmaf(xv.x, wv.x, fmaf(xv.y, wv.y,
                      fmaf(xv.z, wv.z, xv.w * wv.w)));
            acc[e] += s;
        }
    }
    #pragma unroll
    for (int e = 0; e < NPROJ; e++) {
        float v = acc[e];
        v += __shfl_xor_sync(0xffffffffu, v, 16);
        v += __shfl_xor_sync(0xffffffffu, v, 8);
        v += __shfl_xor_sync(0xffffffffu, v, 4);
        v += __shfl_xor_sync(0xffffffffu, v, 2);
        v += __shfl_xor_sync(0xffffffffu, v, 1);
        if (lane == (e & 31)) proj[(size_t)warp * NPROJ + e] = v;
    }
}

// ---------------- dt precompute: dt[m][d] = softplus(dtraw_m*dtw_d+dtb_d) -----
__global__ void dt_kernel(const float* __restrict__ proj,
                          const float* __restrict__ dt_w,
                          const float* __restrict__ dt_b,
                          float* __restrict__ dt)
{
    int idx = blockIdx.x * blockDim.x + threadIdx.x;
    if (idx >= M_TOT * D_INNER) return;
    int d = idx & (D_INNER - 1);
    int m = idx >> 11;
    float s = fmaf(proj[(size_t)m * NPROJ], dt_w[d], dt_b[d]);
    dt[idx] = (s > 20.f) ? s : log1pf(__expf(s));
}

// ---------------- chunked selective scan -------------------------------------
__global__ void __launch_bounds__(256)
scan_pass1(const float* __restrict__ proj, const float* __restrict__ xc,
           const float* __restrict__ dt, const float* __restrict__ A_log,
           float* __restrict__ P, float* __restrict__ Q)
{
    int wg   = (blockIdx.x * blockDim.x + threadIdx.x) >> 5;
    int lane = threadIdx.x & 31;
    int n    = lane & 15;
    int pair = wg >> 3;
    int c    = wg & (CHUNKS - 1);
    if (pair >= BSZ * D_INNER / 2) return;
    int q  = pair * 2 + (lane >> 4);
    int b  = q >> 11;
    int d  = q & (D_INNER - 1);

    const float An = -expf(A_log[d * D_STATE + n]);

    float Pp = 1.f, acc = 0.f;
    const int t0 = c * CHUNK_T;
    const float* pr0 = proj + (size_t)(b * LEN + t0) * NPROJ;
    const float* xc0 = xc + (size_t)(b * LEN + t0) * D_INNER + d;
    const float* dt0 = dt + (size_t)(b * LEN + t0) * D_INNER + d;

    #pragma unroll 2
    for (int t = 0; t < CHUNK_T; t++) {
        float Bn  = pr0[(size_t)t * NPROJ + 1 + n];
        float xcv = xc0[(size_t)t * D_INNER];
        float dtv = dt0[(size_t)t * D_INNER];
        float dA  = __expf(dtv * An);
        acc = fmaf(dA, acc, dtv * Bn * xcv);
        Pp *= dA;
    }
    size_t o = ((size_t)((b * CHUNKS + c) * D_INNER) + d) * D_STATE + n;
    P[o] = Pp;
    Q[o] = acc;
}

__global__ void __launch_bounds__(256)
scan_pass2(const float* __restrict__ P, const float* __restrict__ Q,
           float* __restrict__ H)
{
    int i = blockIdx.x * blockDim.x + threadIdx.x;
    if (i >= BSZ * D_INNER * D_STATE) return;
    int n = i & 15;
    int d = (i >> 4) & (D_INNER - 1);
    int b = i >> 15;

    float h = 0.f;
    #pragma unroll
    for (int c = 0; c < CHUNKS; c++) {
        size_t o = ((size_t)((b * CHUNKS + c) * D_INNER) + d) * D_STATE + n;
        H[o] = h;
        h = fmaf(P[o], h, Q[o]);
    }
}

__global__ void __launch_bounds__(256)
scan_pass3(const float* __restrict__ proj, const float* __restrict__ xc,
           const float* __restrict__ xz, const float* __restrict__ dt,
           const float* __restrict__ A_log, const float* __restrict__ Dp,
           const float* __restrict__ H,
           __nv_bfloat16* __restrict__ Yhi, __nv_bfloat16* __restrict__ Ylo)
{
    int wg   = (blockIdx.x * blockDim.x + threadIdx.x) >> 5;
    int lane = threadIdx.x & 31;
    int n    = lane & 15;
    int pair = wg >> 3;
    int c    = wg & (CHUNKS - 1);
    if (pair >= BSZ * D_INNER / 2) return;
    int q  = pair * 2 + (lane >> 4);
    int b  = q >> 11;
    int d  = q & (D_INNER - 1);

    const float An = -expf(A_log[d * D_STATE + n]);
    const float Dd = Dp[d];

    float h = H[((size_t)((b * CHUNKS + c) * D_INNER) + d) * D_STATE + n];

    const int t0 = c * CHUNK_T;
    const float* pr0 = proj + (size_t)(b * LEN + t0) * NPROJ;
    const float* xc0 = xc + (size_t)(b * LEN + t0) * D_INNER + d;
    const float* dt0 = dt + (size_t)(b * LEN + t0) * D_INNER + d;
    const float* z0  = xz + (size_t)(b * LEN + t0) * (2 * D_INNER) + D_INNER + d;
    __nv_bfloat16* Yh0 = Yhi + (size_t)(b * LEN + t0) * D_INNER + d;
    __nv_bfloat16* Yl0 = Ylo + (size_t)(b * LEN + t0) * D_INNER + d;

    #pragma unroll 2
    for (int t = 0; t < CHUNK_T; t++) {
        float Bn  = pr0[(size_t)t * NPROJ + 1 + n];
        float Cn  = pr0[(size_t)t * NPROJ + 1 + D_STATE + n];
        float xcv = xc0[(size_t)t * D_INNER];
        float dtv = dt0[(size_t)t * D_INNER];
        float zv  = z0 [(size_t)t * (2 * D_INNER)];

        float dA = __expf(dtv * An);
        h = fmaf(dA, h, dtv * Bn * xcv);

        float yp = h * Cn;
        yp += __shfl_xor_sync(0xffffffffu, yp, 8);
        yp += __shfl_xor_sync(0xffffffffu, yp, 4);
        yp += __shfl_xor_sync(0xffffffffu, yp, 2);
        yp += __shfl_xor_sync(0xffffffffu, yp, 1);

        if (n == 0) {
            float sig = 1.f / (1.f + __expf(-zv));
            float yv = (yp + xcv * Dd) * (zv * sig);
            __nv_bfloat16 hv = __float2bfloat16(yv);
            Yh0[(size_t)t * D_INNER] = hv;
            Yl0[(size_t)t * D_INNER] = __float2bfloat16(yv - __bfloat162float(hv));
        }
    }
}

// ---------------- launch -----------------------------------------------------
extern "C" void kernel_launch(void* const* d_in, const int* in_sizes, int n_in,
                              void* d_out, int out_size)
{
    const float* x      = (const float*)d_in[0];
    const float* W_in   = (const float*)d_in[1];
    const float* conv_w = (const float*)d_in[2];
    const float* conv_b = (const float*)d_in[3];
    const float* W_x    = (const float*)d_in[4];
    const float* dt_w   = (const float*)d_in[5];
    const float* dt_b   = (const float*)d_in[6];
    const float* A_log  = (const float*)d_in[7];
    const float* D_par  = (const float*)d_in[8];
    const float* W_out  = (const float*)d_in[9];
    float* out = (float*)d_out;

    float *xz, *xc, *proj, *dtb_, *P, *Qc, *H;
    __nv_bfloat16 *xhi, *xlo, *w1hi, *w1lo, *w2hi, *w2lo, *yhi, *ylo;
    cudaGetSymbolAddress((void**)&xz,   g_xz);
    cudaGetSymbolAddress((void**)&xc,   g_xc);
    cudaGetSymbolAddress((void**)&proj, g_proj);
    cudaGetSymbolAddress((void**)&dtb_, g_dt);
    cudaGetSymbolAddress((void**)&P,    g_P);
    cudaGetSymbolAddress((void**)&Qc,   g_Qc);
    cudaGetSymbolAddress((void**)&H,    g_H);
    cudaGetSymbolAddress((void**)&xhi,  g_xhi);
    cudaGetSymbolAddress((void**)&xlo,  g_xlo);
    cudaGetSymbolAddress((void**)&w1hi, g_w1hi);
    cudaGetSymbolAddress((void**)&w1lo, g_w1lo);
    cudaGetSymbolAddress((void**)&w2hi, g_w2hi);
    cudaGetSymbolAddress((void**)&w2lo, g_w2lo);
    cudaGetSymbolAddress((void**)&yhi,  g_yhi);
    cudaGetSymbolAddress((void**)&ylo,  g_ylo);

    cudaFuncSetAttribute(mma_gemm_nt, cudaFuncAttributeMaxDynamicSharedMemorySize,
                         GEMM_SMEM);

    // 0) hi/lo splits
    {
        int n4;
        n4 = (M_TOT * D_MODEL) / 4;
        split_kernel<<<(n4 + 255) / 256, 256>>>(x, xhi, xlo, n4);
        n4 = (2 * D_INNER * D_MODEL) / 4;
        split_kernel<<<(n4 + 255) / 256, 256>>>(W_in, w1hi, w1lo, n4);
        n4 = (D_MODEL * D_INNER) / 4;
        split_kernel<<<(n4 + 255) / 256, 256>>>(W_out, w2hi, w2lo, n4);
    }
    // 1) xz = x @ W_in^T
    {
        dim3 grid(2 * D_INNER / 128, M_TOT / 128);
        mma_gemm_nt<<<grid, 256, GEMM_SMEM>>>(xhi, xlo, w1hi, w1lo, xz,
                                              M_TOT, 2 * D_INNER, D_MODEL);
    }
    // 2) conv + silu
    {
        int total = M_TOT * D_INNER;
        conv_silu_kernel<<<(total + 255) / 256, 256>>>(xz, conv_w, conv_b, xc);
    }
    // 3) proj = xc @ W_x^T
    {
        xproj_kernel<<<M_TOT / 8, 256>>>(xc, W_x, proj);
    }
    // 3b) dt precompute
    {
        int total = M_TOT * D_INNER;
        dt_kernel<<<(total + 255) / 256, 256>>>(proj, dt_w, dt_b, dtb_);
    }
    // 4) chunked scan
    {
        int nwarp = (BSZ * D_INNER / 2) * CHUNKS;
        scan_pass1<<<nwarp / 8, 256>>>(proj, xc, dtb_, A_log, P, Qc);
        scan_pass2<<<(BSZ * D_INNER * D_STATE) / 256, 256>>>(P, Qc, H);
        scan_pass3<<<nwarp / 8, 256>>>(proj, xc, xz, dtb_, A_log, D_par,
                                       H, yhi, ylo);
    }
    // 5) out = Y @ W_out^T
    {
        dim3 grid(D_MODEL / 128, M_TOT / 128);
        mma_gemm_nt<<<grid, 256, GEMM_SMEM>>>(yhi, ylo, w2hi, w2lo, out,
                                              M_TOT, D_MODEL, D_INNER);
    }
}

// round 6
// speedup vs baseline: 3.3520x; 1.2459x over previous
#include <cuda_runtime.h>
#include <cuda_bf16.h>
#include <math.h>
#include <stdint.h>

#define D_MODEL 1024
#define D_STATE 16
#define D_INNER 2048
#define BSZ     2
#define LEN     1024
#define M_TOT   (BSZ*LEN)
#define NPROJ   (2*D_STATE+1)
#define PSTRIDE 36
#define CHUNKS  16
#define CHUNK_T (LEN/CHUNKS)

// ---------------- scratch --------------------------------------------------
__device__ float g_xz[(size_t)M_TOT * 2 * D_INNER];
__device__ float g_xc[(size_t)M_TOT * D_INNER];
__device__ float g_proj[(size_t)M_TOT * PSTRIDE];
__device__ float g_dt[(size_t)M_TOT * D_INNER];
__device__ float g_P [(size_t)BSZ * CHUNKS * D_INNER * D_STATE];
__device__ float g_Qc[(size_t)BSZ * CHUNKS * D_INNER * D_STATE];
__device__ float g_H [(size_t)BSZ * CHUNKS * D_INNER * D_STATE];
__device__ __nv_bfloat16 g_xhi[(size_t)M_TOT * D_MODEL];
__device__ __nv_bfloat16 g_xlo[(size_t)M_TOT * D_MODEL];
__device__ __nv_bfloat16 g_w1hi[(size_t)2 * D_INNER * D_MODEL];
__device__ __nv_bfloat16 g_w1lo[(size_t)2 * D_INNER * D_MODEL];
__device__ __nv_bfloat16 g_w2hi[(size_t)D_MODEL * D_INNER];
__device__ __nv_bfloat16 g_w2lo[(size_t)D_MODEL * D_INNER];
__device__ __nv_bfloat16 g_yhi[(size_t)M_TOT * D_INNER];
__device__ __nv_bfloat16 g_ylo[(size_t)M_TOT * D_INNER];

// ---------------- helpers ----------------------------------------------------
__device__ __forceinline__ uint32_t smem_u32(const void* p) {
    uint32_t a;
    asm("{ .reg .u64 t; cvta.to.shared.u64 t, %1; cvt.u32.u64 %0, t; }"
        : "=r"(a) : "l"(p));
    return a;
}
__device__ __forceinline__ uint32_t sw128(uint32_t off) {
    return off ^ ((off >> 3) & 0x70);
}
__device__ __forceinline__ uint32_t pack_bf2(float f0, float f1) {
    uint32_t r;
    asm("cvt.rn.bf16x2.f32 %0, %1, %2;" : "=r"(r) : "f"(f1), "f"(f0));
    return r;
}
__device__ __forceinline__ void ldsm4(uint32_t* r, uint32_t addr) {
    asm volatile("ldmatrix.sync.aligned.m8n8.x4.shared.b16 {%0,%1,%2,%3}, [%4];"
        : "=r"(r[0]), "=r"(r[1]), "=r"(r[2]), "=r"(r[3]) : "r"(addr));
}
__device__ __forceinline__ void mma_bf16(float* d, const uint32_t* a,
                                         const uint32_t* b) {
    asm volatile(
        "mma.sync.aligned.m16n8k16.row.col.f32.bf16.bf16.f32 "
        "{%0,%1,%2,%3}, {%4,%5,%6,%7}, {%8,%9}, {%0,%1,%2,%3};"
        : "+f"(d[0]), "+f"(d[1]), "+f"(d[2]), "+f"(d[3])
        : "r"(a[0]), "r"(a[1]), "r"(a[2]), "r"(a[3]), "r"(b[0]), "r"(b[1]));
}
__device__ __forceinline__ void cp16(uint32_t dst, const void* src) {
    asm volatile("cp.async.cg.shared.global [%0], [%1], 16;"
                 :: "r"(dst), "l"(src));
}

// ---------------- hi/lo split ------------------------------------------------
__global__ void split_kernel(const float* __restrict__ in,
                             __nv_bfloat16* __restrict__ hi,
                             __nv_bfloat16* __restrict__ lo, int n4)
{
    int i = blockIdx.x * blockDim.x + threadIdx.x;
    if (i >= n4) return;
    float4 v = ((const float4*)in)[i];
    float hx = __bfloat162float(__float2bfloat16(v.x));
    float hy = __bfloat162float(__float2bfloat16(v.y));
    float hz = __bfloat162float(__float2bfloat16(v.z));
    float hw = __bfloat162float(__float2bfloat16(v.w));
    uint2 h, l;
    h.x = pack_bf2(v.x, v.y);  h.y = pack_bf2(v.z, v.w);
    l.x = pack_bf2(v.x - hx, v.y - hy);
    l.y = pack_bf2(v.z - hz, v.w - hw);
    ((uint2*)hi)[i] = h;
    ((uint2*)lo)[i] = l;
}

// ---------------- mma.sync GEMM (NT), 3-stage cp.async pipeline ---------------
#define OFF_AHI 0
#define OFF_ALO 16384
#define OFF_BHI 32768
#define OFF_BLO 49152
#define STAGE_BYTES 65536
#define STAGES 3
#define GEMM_SMEM (1024 + STAGES*STAGE_BYTES)

__global__ void __launch_bounds__(256)
mma_gemm_nt(const __nv_bfloat16* __restrict__ Ahi, const __nv_bfloat16* __restrict__ Alo,
            const __nv_bfloat16* __restrict__ Bhi, const __nv_bfloat16* __restrict__ Blo,
            float* __restrict__ C, int M, int N, int K)
{
    extern __shared__ char smc[];
    const uint32_t smb0 = smem_u32(smc);
    const uint32_t smb  = (smb0 + 1023) & ~1023u;

    const int tid = threadIdx.x, wid = tid >> 5, lane = tid & 31;
    const int row0 = blockIdx.y * 128, col0 = blockIdx.x * 128;
    const int wm = (wid & 3) * 32;
    const int wn = (wid >> 2) * 64;

    float acc[2][8][4];
    #pragma unroll
    for (int a = 0; a < 2; a++)
        #pragma unroll
        for (int b = 0; b < 8; b++)
            #pragma unroll
            for (int c = 0; c < 4; c++) acc[a][b][c] = 0.f;

    const int lj = lane >> 3;
    const int lr = lane & 7;
    const int nchunk = K >> 6;

    auto load_chunk = [&](int kc, int stage) {
        const __nv_bfloat16* pAh = Ahi + (size_t)row0 * K + kc * 64;
        const __nv_bfloat16* pAl = Alo + (size_t)row0 * K + kc * 64;
        const __nv_bfloat16* pBh = Bhi + (size_t)col0 * K + kc * 64;
        const __nv_bfloat16* pBl = Blo + (size_t)col0 * K + kc * 64;
        uint32_t sb = smb + stage * STAGE_BYTES;
        #pragma unroll
        for (int i = 0; i < 4; i++) {
            int ch = tid + 256 * i;
            int r = ch >> 3, c = ch & 7;
            uint32_t so = sw128((uint32_t)(r * 128 + c * 16));
            size_t g = (size_t)r * K + c * 8;
            cp16(sb + OFF_AHI + so, pAh + g);
            cp16(sb + OFF_ALO + so, pAl + g);
            cp16(sb + OFF_BHI + so, pBh + g);
            cp16(sb + OFF_BLO + so, pBl + g);
        }
        asm volatile("cp.async.commit_group;" ::: "memory");
    };

    load_chunk(0, 0);
    if (nchunk > 1) load_chunk(1, 1);

    for (int kc = 0; kc < nchunk; kc++) {
        asm volatile("cp.async.wait_group %0;" :: "n"(STAGES - 2) : "memory");
        __syncthreads();
        if (kc + STAGES - 1 < nchunk)
            load_chunk(kc + STAGES - 1, (kc + STAGES - 1) % STAGES);

        uint32_t sb = smb + (kc % STAGES) * STAGE_BYTES;
        #pragma unroll
        for (int ks = 0; ks < 4; ks++) {
            uint32_t ah[2][4], al[2][4];
            #pragma unroll
            for (int mt = 0; mt < 2; mt++) {
                int rr = wm + mt * 16 + (lj & 1) * 8 + lr;
                int kb = ks * 32 + (lj >> 1) * 16;
                uint32_t so = sw128((uint32_t)(rr * 128 + kb));
                ldsm4(ah[mt], sb + OFF_AHI + so);
                ldsm4(al[mt], sb + OFF_ALO + so);
            }
            uint32_t bh[4][4], bl[4][4];
            #pragma unroll
            for (int np = 0; np < 4; np++) {
                int rr = wn + np * 16 + (lj >> 1) * 8 + lr;
                int kb = ks * 32 + (lj & 1) * 16;
                uint32_t so = sw128((uint32_t)(rr * 128 + kb));
                ldsm4(bh[np], sb + OFF_BHI + so);
                ldsm4(bl[np], sb + OFF_BLO + so);
            }
            #pragma unroll
            for (int mt = 0; mt < 2; mt++) {
                #pragma unroll
                for (int np = 0; np < 4; np++) {
                    mma_bf16(acc[mt][2*np+0], ah[mt], &bh[np][0]);
                    mma_bf16(acc[mt][2*np+0], ah[mt], &bl[np][0]);
                    mma_bf16(acc[mt][2*np+0], al[mt], &bh[np][0]);
                    mma_bf16(acc[mt][2*np+1], ah[mt], &bh[np][2]);
                    mma_bf16(acc[mt][2*np+1], ah[mt], &bl[np][2]);
                    mma_bf16(acc[mt][2*np+1], al[mt], &bh[np][2]);
                }
            }
        }
    }

    #pragma unroll
    for (int mt = 0; mt < 2; mt++) {
        int row = row0 + wm + mt * 16 + (lane >> 2);
        #pragma unroll
        for (int nt = 0; nt < 8; nt++) {
            int col = col0 + wn + nt * 8 + 2 * (lane & 3);
            float2 v0 = make_float2(acc[mt][nt][0], acc[mt][nt][1]);
            float2 v1 = make_float2(acc[mt][nt][2], acc[mt][nt][3]);
            *(float2*)(C + (size_t)row * N + col) = v0;
            *(float2*)(C + (size_t)(row + 8) * N + col) = v1;
        }
    }
}

// ---------------- causal depthwise conv (K=4) + SiLU ------------------------
__global__ void conv_silu_kernel(const float* __restrict__ xz,
                                 const float* __restrict__ cw,
                                 const float* __restrict__ cb,
                                 float* __restrict__ xc)
{
    int idx = blockIdx.x * blockDim.x + threadIdx.x;
    if (idx >= M_TOT * D_INNER) return;
    int d = idx & (D_INNER - 1);
    int m = idx >> 11;
    int l = m & (LEN - 1);

    const float w0 = cw[d * 4 + 0], w1 = cw[d * 4 + 1];
    const float w2 = cw[d * 4 + 2], w3 = cw[d * 4 + 3];
    const float* base = xz + (size_t)m * (2 * D_INNER) + d;
    const int stride = 2 * D_INNER;

    float acc = cb[d] + w3 * base[0];
    if (l >= 1) acc += w2 * base[-stride];
    if (l >= 2) acc += w1 * base[-2 * stride];
    if (l >= 3) acc += w0 * base[-3 * stride];

    float sig = 1.f / (1.f + __expf(-acc));
    xc[idx] = acc * sig;
}

// ---------------- x-proj (padded output layout, stride 36) --------------------
// proj row: [0]=dt_raw, [4..19]=B, [20..35]=C
__global__ void __launch_bounds__(256)
xproj_kernel(const float* __restrict__ xc, const float* __restrict__ Wx,
             float* __restrict__ proj)
{
    int warp = (blockIdx.x * blockDim.x + threadIdx.x) >> 5;
    int lane = threadIdx.x & 31;
    if (warp >= M_TOT) return;

    const float4* xr = (const float4*)(xc + (size_t)warp * D_INNER);
    float acc[NPROJ];
    #pragma unroll
    for (int e = 0; e < NPROJ; e++) acc[e] = 0.f;

    for (int k4 = lane; k4 < D_INNER / 4; k4 += 32) {
        float4 xv = xr[k4];
        #pragma unroll
        for (int e = 0; e < NPROJ; e++) {
            float4 wv = ((const float4*)(Wx + (size_t)e * D_INNER))[k4];
            float s = fmaf(xv.x, wv.x, fmaf(xv.y, wv.y,
                      fmaf(xv.z, wv.z, xv.w * wv.w)));
            acc[e] += s;
        }
    }
    #pragma unroll
    for (int e = 0; e < NPROJ; e++) {
        float v = acc[e];
        v += __shfl_xor_sync(0xffffffffu, v, 16);
        v += __shfl_xor_sync(0xffffffffu, v, 8);
        v += __shfl_xor_sync(0xffffffffu, v, 4);
        v += __shfl_xor_sync(0xffffffffu, v, 2);
        v += __shfl_xor_sync(0xffffffffu, v, 1);
        int off = (e == 0) ? 0 : (e + 3);
        if (lane == (e & 31)) proj[(size_t)warp * PSTRIDE + off] = v;
    }
}

// ---------------- dt precompute ------------------------------------------------
__global__ void dt_kernel(const float* __restrict__ proj,
                          const float* __restrict__ dt_w,
                          const float* __restrict__ dt_b,
                          float* __restrict__ dt)
{
    int idx = blockIdx.x * blockDim.x + threadIdx.x;
    if (idx >= M_TOT * D_INNER) return;
    int d = idx & (D_INNER - 1);
    int m = idx >> 11;
    float s = fmaf(proj[(size_t)m * PSTRIDE], dt_w[d], dt_b[d]);
    dt[idx] = (s > 20.f) ? s : log1pf(__expf(s));
}

// ---------------- chunked selective scan -------------------------------------
// Warp = 8 channels x 1 chunk. lane = ch*4 + sg; lane owns states sg*4..sg*4+3.
__global__ void __launch_bounds__(256)
scan_pass1(const float* __restrict__ proj, const float* __restrict__ xc,
           const float* __restrict__ dt, const float* __restrict__ A_log,
           float* __restrict__ P, float* __restrict__ Q)
{
    int wg   = (blockIdx.x * blockDim.x + threadIdx.x) >> 5;
    int lane = threadIdx.x & 31;
    int grp  = wg >> 4;               // channel-group (8 ch each)
    int c    = wg & (CHUNKS - 1);
    if (grp >= BSZ * D_INNER / 8) return;
    int ch = lane >> 2, sg = lane & 3, n0 = sg * 4;
    int q  = grp * 8 + ch;
    int b  = q >> 11;
    int d  = q & (D_INNER - 1);

    float4 al = *(const float4*)(A_log + d * D_STATE + n0);
    float An0 = -expf(al.x), An1 = -expf(al.y);
    float An2 = -expf(al.z), An3 = -expf(al.w);

    const int m0 = b * LEN + c * CHUNK_T;
    const float4* pB  = (const float4*)(proj + (size_t)m0 * PSTRIDE + 4 + n0);
    const float*  xcp = xc + (size_t)m0 * D_INNER + d;
    const float*  dtp = dt + (size_t)m0 * D_INNER + d;

    float h0 = 0.f, h1 = 0.f, h2 = 0.f, h3 = 0.f;
    float P0 = 1.f, P1 = 1.f, P2 = 1.f, P3 = 1.f;

    #pragma unroll 4
    for (int t = 0; t < CHUNK_T; t++) {
        float4 Bv = *pB;
        float xcv = *xcp, dtv = *dtp;
        float u = dtv * xcv;
        float dA0 = __expf(dtv * An0);
        float dA1 = __expf(dtv * An1);
        float dA2 = __expf(dtv * An2);
        float dA3 = __expf(dtv * An3);
        h0 = fmaf(dA0, h0, u * Bv.x);  P0 *= dA0;
        h1 = fmaf(dA1, h1, u * Bv.y);  P1 *= dA1;
        h2 = fmaf(dA2, h2, u * Bv.z);  P2 *= dA2;
        h3 = fmaf(dA3, h3, u * Bv.w);  P3 *= dA3;
        pB += PSTRIDE / 4;
        xcp += D_INNER;
        dtp += D_INNER;
    }
    size_t o = ((size_t)((b * CHUNKS + c) * D_INNER) + d) * D_STATE + n0;
    *(float4*)(P + o) = make_float4(P0, P1, P2, P3);
    *(float4*)(Q + o) = make_float4(h0, h1, h2, h3);
}

__global__ void __launch_bounds__(256)
scan_pass2(const float* __restrict__ P, const float* __restrict__ Q,
           float* __restrict__ H)
{
    int i = blockIdx.x * blockDim.x + threadIdx.x;
    if (i >= BSZ * D_INNER * D_STATE) return;
    int n = i & 15;
    int d = (i >> 4) & (D_INNER - 1);
    int b = i >> 15;

    float h = 0.f;
    #pragma unroll
    for (int c = 0; c < CHUNKS; c++) {
        size_t o = ((size_t)((b * CHUNKS + c) * D_INNER) + d) * D_STATE + n;
        H[o] = h;
        h = fmaf(P[o], h, Q[o]);
    }
}

__global__ void __launch_bounds__(256)
scan_pass3(const float* __restrict__ proj, const float* __restrict__ xc,
           const float* __restrict__ xz, const float* __restrict__ dt,
           const float* __restrict__ A_log, const float* __restrict__ Dp,
           const float* __restrict__ H,
           __nv_bfloat16* __restrict__ Yhi, __nv_bfloat16* __restrict__ Ylo)
{
    int wg   = (blockIdx.x * blockDim.x + threadIdx.x) >> 5;
    int lane = threadIdx.x & 31;
    int grp  = wg >> 4;
    int c    = wg & (CHUNKS - 1);
    if (grp >= BSZ * D_INNER / 8) return;
    int ch = lane >> 2, sg = lane & 3, n0 = sg * 4;
    int q  = grp * 8 + ch;
    int b  = q >> 11;
    int d  = q & (D_INNER - 1);

    float4 al = *(const float4*)(A_log + d * D_STATE + n0);
    float An0 = -expf(al.x), An1 = -expf(al.y);
    float An2 = -expf(al.z), An3 = -expf(al.w);
    const float Dd = Dp[d];

    float4 hv4 = *(const float4*)(H + ((size_t)((b * CHUNKS + c) * D_INNER) + d) * D_STATE + n0);
    float h0 = hv4.x, h1 = hv4.y, h2 = hv4.z, h3 = hv4.w;

    const int m0 = b * LEN + c * CHUNK_T;
    const float4* pB  = (const float4*)(proj + (size_t)m0 * PSTRIDE + 4 + n0);
    const float4* pC  = (const float4*)(proj + (size_t)m0 * PSTRIDE + 20 + n0);
    const float*  xcp = xc + (size_t)m0 * D_INNER + d;
    const float*  dtp = dt + (size_t)m0 * D_INNER + d;
    const float*  zp  = xz + (size_t)m0 * (2 * D_INNER) + D_INNER + d;
    __nv_bfloat16* Yh = Yhi + (size_t)m0 * D_INNER + d;
    __nv_bfloat16* Yl = Ylo + (size_t)m0 * D_INNER + d;

    #pragma unroll 2
    for (int t = 0; t < CHUNK_T; t++) {
        float4 Bv = *pB;
        float4 Cv = *pC;
        float xcv = *xcp, dtv = *dtp, zv = *zp;
        float u = dtv * xcv;
        float dA0 = __expf(dtv * An0);
        float dA1 = __expf(dtv * An1);
        float dA2 = __expf(dtv * An2);
        float dA3 = __expf(dtv * An3);
        h0 = fmaf(dA0, h0, u * Bv.x);
        h1 = fmaf(dA1, h1, u * Bv.y);
        h2 = fmaf(dA2, h2, u * Bv.z);
        h3 = fmaf(dA3, h3, u * Bv.w);

        float y = fmaf(h0, Cv.x, fmaf(h1, Cv.y, fmaf(h2, Cv.z, h3 * Cv.w)));
        y += __shfl_xor_sync(0xffffffffu, y, 1);
        y += __shfl_xor_sync(0xffffffffu, y, 2);

        if (sg == 0) {
            float sig = 1.f / (1.f + __expf(-zv));
            float yv = (y + xcv * Dd) * (zv * sig);
            __nv_bfloat16 hb = __float2bfloat16(yv);
            *Yh = hb;
            *Yl = __float2bfloat16(yv - __bfloat162float(hb));
        }
        pB += PSTRIDE / 4;
        pC += PSTRIDE / 4;
        xcp += D_INNER;
        dtp += D_INNER;
        zp  += 2 * D_INNER;
        Yh  += D_INNER;
        Yl  += D_INNER;
    }
}

// ---------------- launch -----------------------------------------------------
extern "C" void kernel_launch(void* const* d_in, const int* in_sizes, int n_in,
                              void* d_out, int out_size)
{
    const float* x      = (const float*)d_in[0];
    const float* W_in   = (const float*)d_in[1];
    const float* conv_w = (const float*)d_in[2];
    const float* conv_b = (const float*)d_in[3];
    const float* W_x    = (const float*)d_in[4];
    const float* dt_w   = (const float*)d_in[5];
    const float* dt_b   = (const float*)d_in[6];
    const float* A_log  = (const float*)d_in[7];
    const float* D_par  = (const float*)d_in[8];
    const float* W_out  = (const float*)d_in[9];
    float* out = (float*)d_out;

    float *xz, *xc, *proj, *dtb_, *P, *Qc, *H;
    __nv_bfloat16 *xhi, *xlo, *w1hi, *w1lo, *w2hi, *w2lo, *yhi, *ylo;
    cudaGetSymbolAddress((void**)&xz,   g_xz);
    cudaGetSymbolAddress((void**)&xc,   g_xc);
    cudaGetSymbolAddress((void**)&proj, g_proj);
    cudaGetSymbolAddress((void**)&dtb_, g_dt);
    cudaGetSymbolAddress((void**)&P,    g_P);
    cudaGetSymbolAddress((void**)&Qc,   g_Qc);
    cudaGetSymbolAddress((void**)&H,    g_H);
    cudaGetSymbolAddress((void**)&xhi,  g_xhi);
    cudaGetSymbolAddress((void**)&xlo,  g_xlo);
    cudaGetSymbolAddress((void**)&w1hi, g_w1hi);
    cudaGetSymbolAddress((void**)&w1lo, g_w1lo);
    cudaGetSymbolAddress((void**)&w2hi, g_w2hi);
    cudaGetSymbolAddress((void**)&w2lo, g_w2lo);
    cudaGetSymbolAddress((void**)&yhi,  g_yhi);
    cudaGetSymbolAddress((void**)&ylo,  g_ylo);

    cudaFuncSetAttribute(mma_gemm_nt, cudaFuncAttributeMaxDynamicSharedMemorySize,
                         GEMM_SMEM);

    // 0) hi/lo splits
    {
        int n4;
        n4 = (M_TOT * D_MODEL) / 4;
        split_kernel<<<(n4 + 255) / 256, 256>>>(x, xhi, xlo, n4);
        n4 = (2 * D_INNER * D_MODEL) / 4;
        split_kernel<<<(n4 + 255) / 256, 256>>>(W_in, w1hi, w1lo, n4);
        n4 = (D_MODEL * D_INNER) / 4;
        split_kernel<<<(n4 + 255) / 256, 256>>>(W_out, w2hi, w2lo, n4);
    }
    // 1) xz = x @ W_in^T
    {
        dim3 grid(2 * D_INNER / 128, M_TOT / 128);
        mma_gemm_nt<<<grid, 256, GEMM_SMEM>>>(xhi, xlo, w1hi, w1lo, xz,
                                              M_TOT, 2 * D_INNER, D_MODEL);
    }
    // 2) conv + silu
    {
        int total = M_TOT * D_INNER;
        conv_silu_kernel<<<(total + 255) / 256, 256>>>(xz, conv_w, conv_b, xc);
    }
    // 3) proj = xc @ W_x^T (padded layout)
    {
        xproj_kernel<<<M_TOT / 8, 256>>>(xc, W_x, proj);
    }
    // 3b) dt precompute
    {
        int total = M_TOT * D_INNER;
        dt_kernel<<<(total + 255) / 256, 256>>>(proj, dt_w, dt_b, dtb_);
    }
    // 4) chunked scan (8 channels per warp)
    {
        int nwarp = (BSZ * D_INNER / 8) * CHUNKS;   // 8192
        scan_pass1<<<nwarp / 8, 256>>>(proj, xc, dtb_, A_log, P, Qc);
        scan_pass2<<<(BSZ * D_INNER * D_STATE) / 256, 256>>>(P, Qc, H);
        scan_pass3<<<nwarp / 8, 256>>>(proj, xc, xz, dtb_, A_log, D_par,
                                       H, yhi, ylo);
    }
    // 5) out = Y @ W_out^T
    {
        dim3 grid(D_MODEL / 128, M_TOT / 128);
        mma_gemm_nt<<<grid, 256, GEMM_SMEM>>>(yhi, ylo, w2hi, w2lo, out,
                                              M_TOT, D_MODEL, D_INNER);
    }
}

// round 7
// speedup vs baseline: 3.3552x; 1.0009x over previous
#include <cuda_runtime.h>
#include <cuda_bf16.h>
#include <math.h>
#include <stdint.h>

#define D_MODEL 1024
#define D_STATE 16
#define D_INNER 2048
#define BSZ     2
#define LEN     1024
#define M_TOT   (BSZ*LEN)
#define NPROJ   (2*D_STATE+1)
#define PSTRIDE 36
#define CHUNKS  16
#define CHUNK_T (LEN/CHUNKS)

// ---------------- scratch --------------------------------------------------
__device__ float g_xz[(size_t)M_TOT * 2 * D_INNER];
__device__ float g_xc[(size_t)M_TOT * D_INNER];
__device__ float g_proj[(size_t)M_TOT * PSTRIDE];
__device__ float g_dt[(size_t)M_TOT * D_INNER];
__device__ float g_P [(size_t)BSZ * CHUNKS * D_INNER * D_STATE];
__device__ float g_Qc[(size_t)BSZ * CHUNKS * D_INNER * D_STATE];
__device__ float g_H [(size_t)BSZ * CHUNKS * D_INNER * D_STATE];
__device__ __nv_bfloat16 g_xhi[(size_t)M_TOT * D_MODEL];
__device__ __nv_bfloat16 g_xlo[(size_t)M_TOT * D_MODEL];
__device__ __nv_bfloat16 g_w1hi[(size_t)2 * D_INNER * D_MODEL];
__device__ __nv_bfloat16 g_w1lo[(size_t)2 * D_INNER * D_MODEL];
__device__ __nv_bfloat16 g_w2hi[(size_t)D_MODEL * D_INNER];
__device__ __nv_bfloat16 g_w2lo[(size_t)D_MODEL * D_INNER];
__device__ __nv_bfloat16 g_yhi[(size_t)M_TOT * D_INNER];
__device__ __nv_bfloat16 g_ylo[(size_t)M_TOT * D_INNER];

// ---------------- helpers ----------------------------------------------------
__device__ __forceinline__ uint32_t smem_u32(const void* p) {
    uint32_t a;
    asm("{ .reg .u64 t; cvta.to.shared.u64 t, %1; cvt.u32.u64 %0, t; }"
        : "=r"(a) : "l"(p));
    return a;
}
__device__ __forceinline__ uint32_t sw128(uint32_t off) {
    return off ^ ((off >> 3) & 0x70);
}
__device__ __forceinline__ uint32_t pack_bf2(float f0, float f1) {
    uint32_t r;
    asm("cvt.rn.bf16x2.f32 %0, %1, %2;" : "=r"(r) : "f"(f1), "f"(f0));
    return r;
}
__device__ __forceinline__ void ldsm4(uint32_t* r, uint32_t addr) {
    asm volatile("ldmatrix.sync.aligned.m8n8.x4.shared.b16 {%0,%1,%2,%3}, [%4];"
        : "=r"(r[0]), "=r"(r[1]), "=r"(r[2]), "=r"(r[3]) : "r"(addr));
}
__device__ __forceinline__ void mma_bf16(float* d, const uint32_t* a,
                                         const uint32_t* b) {
    asm volatile(
        "mma.sync.aligned.m16n8k16.row.col.f32.bf16.bf16.f32 "
        "{%0,%1,%2,%3}, {%4,%5,%6,%7}, {%8,%9}, {%0,%1,%2,%3};"
        : "+f"(d[0]), "+f"(d[1]), "+f"(d[2]), "+f"(d[3])
        : "r"(a[0]), "r"(a[1]), "r"(a[2]), "r"(a[3]), "r"(b[0]), "r"(b[1]));
}
__device__ __forceinline__ void cp16(uint32_t dst, const void* src) {
    asm volatile("cp.async.cg.shared.global [%0], [%1], 16;"
                 :: "r"(dst), "l"(src));
}

// ---------------- hi/lo split ------------------------------------------------
__global__ void split_kernel(const float* __restrict__ in,
                             __nv_bfloat16* __restrict__ hi,
                             __nv_bfloat16* __restrict__ lo, int n4)
{
    int i = blockIdx.x * blockDim.x + threadIdx.x;
    if (i >= n4) return;
    float4 v = ((const float4*)in)[i];
    float hx = __bfloat162float(__float2bfloat16(v.x));
    float hy = __bfloat162float(__float2bfloat16(v.y));
    float hz = __bfloat162float(__float2bfloat16(v.z));
    float hw = __bfloat162float(__float2bfloat16(v.w));
    uint2 h, l;
    h.x = pack_bf2(v.x, v.y);  h.y = pack_bf2(v.z, v.w);
    l.x = pack_bf2(v.x - hx, v.y - hy);
    l.y = pack_bf2(v.z - hz, v.w - hw);
    ((uint2*)hi)[i] = h;
    ((uint2*)lo)[i] = l;
}

// ---------------- mma.sync GEMM (NT), 3-stage cp.async pipeline ---------------
// Product passes ordered hh -> hl -> lh so consecutive HMMAs touch 16 distinct
// accumulators (RAW chain distance 16 instead of 2).
#define OFF_AHI 0
#define OFF_ALO 16384
#define OFF_BHI 32768
#define OFF_BLO 49152
#define STAGE_BYTES 65536
#define STAGES 3
#define GEMM_SMEM (1024 + STAGES*STAGE_BYTES)

__global__ void __launch_bounds__(256)
mma_gemm_nt(const __nv_bfloat16* __restrict__ Ahi, const __nv_bfloat16* __restrict__ Alo,
            const __nv_bfloat16* __restrict__ Bhi, const __nv_bfloat16* __restrict__ Blo,
            float* __restrict__ C, int M, int N, int K)
{
    extern __shared__ char smc[];
    const uint32_t smb0 = smem_u32(smc);
    const uint32_t smb  = (smb0 + 1023) & ~1023u;

    const int tid = threadIdx.x, wid = tid >> 5, lane = tid & 31;
    const int row0 = blockIdx.y * 128, col0 = blockIdx.x * 128;
    const int wm = (wid & 3) * 32;
    const int wn = (wid >> 2) * 64;

    float acc[2][8][4];
    #pragma unroll
    for (int a = 0; a < 2; a++)
        #pragma unroll
        for (int b = 0; b < 8; b++)
            #pragma unroll
            for (int c = 0; c < 4; c++) acc[a][b][c] = 0.f;

    const int lj = lane >> 3;
    const int lr = lane & 7;
    const int nchunk = K >> 6;

    auto load_chunk = [&](int kc, int stage) {
        const __nv_bfloat16* pAh = Ahi + (size_t)row0 * K + kc * 64;
        const __nv_bfloat16* pAl = Alo + (size_t)row0 * K + kc * 64;
        const __nv_bfloat16* pBh = Bhi + (size_t)col0 * K + kc * 64;
        const __nv_bfloat16* pBl = Blo + (size_t)col0 * K + kc * 64;
        uint32_t sb = smb + stage * STAGE_BYTES;
        #pragma unroll
        for (int i = 0; i < 4; i++) {
            int ch = tid + 256 * i;
            int r = ch >> 3, c = ch & 7;
            uint32_t so = sw128((uint32_t)(r * 128 + c * 16));
            size_t g = (size_t)r * K + c * 8;
            cp16(sb + OFF_AHI + so, pAh + g);
            cp16(sb + OFF_ALO + so, pAl + g);
            cp16(sb + OFF_BHI + so, pBh + g);
            cp16(sb + OFF_BLO + so, pBl + g);
        }
        asm volatile("cp.async.commit_group;" ::: "memory");
    };

    load_chunk(0, 0);
    if (nchunk > 1) load_chunk(1, 1);

    for (int kc = 0; kc < nchunk; kc++) {
        asm volatile("cp.async.wait_group %0;" :: "n"(STAGES - 2) : "memory");
        __syncthreads();
        if (kc + STAGES - 1 < nchunk)
            load_chunk(kc + STAGES - 1, (kc + STAGES - 1) % STAGES);

        uint32_t sb = smb + (kc % STAGES) * STAGE_BYTES;
        #pragma unroll
        for (int ks = 0; ks < 4; ks++) {
            uint32_t ah[2][4], al[2][4];
            #pragma unroll
            for (int mt = 0; mt < 2; mt++) {
                int rr = wm + mt * 16 + (lj & 1) * 8 + lr;
                int kb = ks * 32 + (lj >> 1) * 16;
                uint32_t so = sw128((uint32_t)(rr * 128 + kb));
                ldsm4(ah[mt], sb + OFF_AHI + so);
                ldsm4(al[mt], sb + OFF_ALO + so);
            }
            uint32_t bh[4][4], bl[4][4];
            #pragma unroll
            for (int np = 0; np < 4; np++) {
                int rr = wn + np * 16 + (lj >> 1) * 8 + lr;
                int kb = ks * 32 + (lj & 1) * 16;
                uint32_t so = sw128((uint32_t)(rr * 128 + kb));
                ldsm4(bh[np], sb + OFF_BHI + so);
                ldsm4(bl[np], sb + OFF_BLO + so);
            }
            // pass 1: hi*hi  (16 mmas, all-distinct accumulators)
            #pragma unroll
            for (int mt = 0; mt < 2; mt++)
                #pragma unroll
                for (int np = 0; np < 4; np++) {
                    mma_bf16(acc[mt][2*np+0], ah[mt], &bh[np][0]);
                    mma_bf16(acc[mt][2*np+1], ah[mt], &bh[np][2]);
                }
            // pass 2: hi*lo
            #pragma unroll
            for (int mt = 0; mt < 2; mt++)
                #pragma unroll
                for (int np = 0; np < 4; np++) {
                    mma_bf16(acc[mt][2*np+0], ah[mt], &bl[np][0]);
                    mma_bf16(acc[mt][2*np+1], ah[mt], &bl[np][2]);
                }
            // pass 3: lo*hi
            #pragma unroll
            for (int mt = 0; mt < 2; mt++)
                #pragma unroll
                for (int np = 0; np < 4; np++) {
                    mma_bf16(acc[mt][2*np+0], al[mt], &bh[np][0]);
                    mma_bf16(acc[mt][2*np+1], al[mt], &bh[np][2]);
                }
        }
    }

    #pragma unroll
    for (int mt = 0; mt < 2; mt++) {
        int row = row0 + wm + mt * 16 + (lane >> 2);
        #pragma unroll
        for (int nt = 0; nt < 8; nt++) {
            int col = col0 + wn + nt * 8 + 2 * (lane & 3);
            float2 v0 = make_float2(acc[mt][nt][0], acc[mt][nt][1]);
            float2 v1 = make_float2(acc[mt][nt][2], acc[mt][nt][3]);
            *(float2*)(C + (size_t)row * N + col) = v0;
            *(float2*)(C + (size_t)(row + 8) * N + col) = v1;
        }
    }
}

// ---------------- causal depthwise conv (K=4) + SiLU ------------------------
__global__ void conv_silu_kernel(const float* __restrict__ xz,
                                 const float* __restrict__ cw,
                                 const float* __restrict__ cb,
                                 float* __restrict__ xc)
{
    int idx = blockIdx.x * blockDim.x + threadIdx.x;
    if (idx >= M_TOT * D_INNER) return;
    int d = idx & (D_INNER - 1);
    int m = idx >> 11;
    int l = m & (LEN - 1);

    const float w0 = cw[d * 4 + 0], w1 = cw[d * 4 + 1];
    const float w2 = cw[d * 4 + 2], w3 = cw[d * 4 + 3];
    const float* base = xz + (size_t)m * (2 * D_INNER) + d;
    const int stride = 2 * D_INNER;

    float acc = cb[d] + w3 * base[0];
    if (l >= 1) acc += w2 * base[-stride];
    if (l >= 2) acc += w1 * base[-2 * stride];
    if (l >= 3) acc += w0 * base[-3 * stride];

    float sig = 1.f / (1.f + __expf(-acc));
    xc[idx] = acc * sig;
}

// ---------------- x-proj (padded output layout, stride 36) --------------------
__global__ void __launch_bounds__(256)
xproj_kernel(const float* __restrict__ xc, const float* __restrict__ Wx,
             float* __restrict__ proj)
{
    int warp = (blockIdx.x * blockDim.x + threadIdx.x) >> 5;
    int lane = threadIdx.x & 31;
    if (warp >= M_TOT) return;

    const float4* xr = (const float4*)(xc + (size_t)warp * D_INNER);
    float acc[NPROJ];
    #pragma unroll
    for (int e = 0; e < NPROJ; e++) acc[e] = 0.f;

    for (int k4 = lane; k4 < D_INNER / 4; k4 += 32) {
        float4 xv = xr[k4];
        #pragma unroll
        for (int e = 0; e < NPROJ; e++) {
            float4 wv = ((const float4*)(Wx + (size_t)e * D_INNER))[k4];
            float s = fmaf(xv.x, wv.x, fmaf(xv.y, wv.y,
                      fmaf(xv.z, wv.z, xv.w * wv.w)));
            acc[e] += s;
        }
    }
    #pragma unroll
    for (int e = 0; e < NPROJ; e++) {
        float v = acc[e];
        v += __shfl_xor_sync(0xffffffffu, v, 16);
        v += __shfl_xor_sync(0xffffffffu, v, 8);
        v += __shfl_xor_sync(0xffffffffu, v, 4);
        v += __shfl_xor_sync(0xffffffffu, v, 2);
        v += __shfl_xor_sync(0xffffffffu, v, 1);
        int off = (e == 0) ? 0 : (e + 3);
        if (lane == (e & 31)) proj[(size_t)warp * PSTRIDE + off] = v;
    }
}

// ---------------- dt precompute ------------------------------------------------
__global__ void dt_kernel(const float* __restrict__ proj,
                          const float* __restrict__ dt_w,
                          const float* __restrict__ dt_b,
                          float* __restrict__ dt)
{
    int idx = blockIdx.x * blockDim.x + threadIdx.x;
    if (idx >= M_TOT * D_INNER) return;
    int d = idx & (D_INNER - 1);
    int m = idx >> 11;
    float s = fmaf(proj[(size_t)m * PSTRIDE], dt_w[d], dt_b[d]);
    dt[idx] = (s > 20.f) ? s : log1pf(__expf(s));
}

// ---------------- chunked selective scan -------------------------------------
__global__ void __launch_bounds__(256)
scan_pass1(const float* __restrict__ proj, const float* __restrict__ xc,
           const float* __restrict__ dt, const float* __restrict__ A_log,
           float* __restrict__ P, float* __restrict__ Q)
{
    int wg   = (blockIdx.x * blockDim.x + threadIdx.x) >> 5;
    int lane = threadIdx.x & 31;
    int grp  = wg >> 4;
    int c    = wg & (CHUNKS - 1);
    if (grp >= BSZ * D_INNER / 8) return;
    int ch = lane >> 2, sg = lane & 3, n0 = sg * 4;
    int q  = grp * 8 + ch;
    int b  = q >> 11;
    int d  = q & (D_INNER - 1);

    float4 al = *(const float4*)(A_log + d * D_STATE + n0);
    float An0 = -expf(al.x), An1 = -expf(al.y);
    float An2 = -expf(al.z), An3 = -expf(al.w);

    const int m0 = b * LEN + c * CHUNK_T;
    const float4* pB  = (const float4*)(proj + (size_t)m0 * PSTRIDE + 4 + n0);
    const float*  xcp = xc + (size_t)m0 * D_INNER + d;
    const float*  dtp = dt + (size_t)m0 * D_INNER + d;

    float h0 = 0.f, h1 = 0.f, h2 = 0.f, h3 = 0.f;
    float P0 = 1.f, P1 = 1.f, P2 = 1.f, P3 = 1.f;

    #pragma unroll 4
    for (int t = 0; t < CHUNK_T; t++) {
        float4 Bv = *pB;
        float xcv = *xcp, dtv = *dtp;
        float u = dtv * xcv;
        float dA0 = __expf(dtv * An0);
        float dA1 = __expf(dtv * An1);
        float dA2 = __expf(dtv * An2);
        float dA3 = __expf(dtv * An3);
        h0 = fmaf(dA0, h0, u * Bv.x);  P0 *= dA0;
        h1 = fmaf(dA1, h1, u * Bv.y);  P1 *= dA1;
        h2 = fmaf(dA2, h2, u * Bv.z);  P2 *= dA2;
        h3 = fmaf(dA3, h3, u * Bv.w);  P3 *= dA3;
        pB += PSTRIDE / 4;
        xcp += D_INNER;
        dtp += D_INNER;
    }
    size_t o = ((size_t)((b * CHUNKS + c) * D_INNER) + d) * D_STATE + n0;
    *(float4*)(P + o) = make_float4(P0, P1, P2, P3);
    *(float4*)(Q + o) = make_float4(h0, h1, h2, h3);
}

__global__ void __launch_bounds__(256)
scan_pass2(const float* __restrict__ P, const float* __restrict__ Q,
           float* __restrict__ H)
{
    int i = blockIdx.x * blockDim.x + threadIdx.x;
    if (i >= BSZ * D_INNER * D_STATE) return;
    int n = i & 15;
    int d = (i >> 4) & (D_INNER - 1);
    int b = i >> 15;

    float h = 0.f;
    #pragma unroll
    for (int c = 0; c < CHUNKS; c++) {
        size_t o = ((size_t)((b * CHUNKS + c) * D_INNER) + d) * D_STATE + n;
        H[o] = h;
        h = fmaf(P[o], h, Q[o]);
    }
}

__global__ void __launch_bounds__(256)
scan_pass3(const float* __restrict__ proj, const float* __restrict__ xc,
           const float* __restrict__ xz, const float* __restrict__ dt,
           const float* __restrict__ A_log, const float* __restrict__ Dp,
           const float* __restrict__ H,
           __nv_bfloat16* __restrict__ Yhi, __nv_bfloat16* __restrict__ Ylo)
{
    int wg   = (blockIdx.x * blockDim.x + threadIdx.x) >> 5;
    int lane = threadIdx.x & 31;
    int grp  = wg >> 4;
    int c    = wg & (CHUNKS - 1);
    if (grp >= BSZ * D_INNER / 8) return;
    int ch = lane >> 2, sg = lane & 3, n0 = sg * 4;
    int q  = grp * 8 + ch;
    int b  = q >> 11;
    int d  = q & (D_INNER - 1);

    float4 al = *(const float4*)(A_log + d * D_STATE + n0);
    float An0 = -expf(al.x), An1 = -expf(al.y);
    float An2 = -expf(al.z), An3 = -expf(al.w);
    const float Dd = Dp[d];

    float4 hv4 = *(const float4*)(H + ((size_t)((b * CHUNKS + c) * D_INNER) + d) * D_STATE + n0);
    float h0 = hv4.x, h1 = hv4.y, h2 = hv4.z, h3 = hv4.w;

    const int m0 = b * LEN + c * CHUNK_T;
    const float4* pB  = (const float4*)(proj + (size_t)m0 * PSTRIDE + 4 + n0);
    const float4* pC  = (const float4*)(proj + (size_t)m0 * PSTRIDE + 20 + n0);
    const float*  xcp = xc + (size_t)m0 * D_INNER + d;
    const float*  dtp = dt + (size_t)m0 * D_INNER + d;
    const float*  zp  = xz + (size_t)m0 * (2 * D_INNER) + D_INNER + d;
    __nv_bfloat16* Yh = Yhi + (size_t)m0 * D_INNER + d;
    __nv_bfloat16* Yl = Ylo + (size_t)m0 * D_INNER + d;

    #pragma unroll 2
    for (int t = 0; t < CHUNK_T; t++) {
        float4 Bv = *pB;
        float4 Cv = *pC;
        float xcv = *xcp, dtv = *dtp, zv = *zp;
        float u = dtv * xcv;
        float dA0 = __expf(dtv * An0);
        float dA1 = __expf(dtv * An1);
        float dA2 = __expf(dtv * An2);
        float dA3 = __expf(dtv * An3);
        h0 = fmaf(dA0, h0, u * Bv.x);
        h1 = fmaf(dA1, h1, u * Bv.y);
        h2 = fmaf(dA2, h2, u * Bv.z);
        h3 = fmaf(dA3, h3, u * Bv.w);

        float y = fmaf(h0, Cv.x, fmaf(h1, Cv.y, fmaf(h2, Cv.z, h3 * Cv.w)));
        y += __shfl_xor_sync(0xffffffffu, y, 1);
        y += __shfl_xor_sync(0xffffffffu, y, 2);

        if (sg == 0) {
            float sig = 1.f / (1.f + __expf(-zv));
            float yv = (y + xcv * Dd) * (zv * sig);
            __nv_bfloat16 hb = __float2bfloat16(yv);
            *Yh = hb;
            *Yl = __float2bfloat16(yv - __bfloat162float(hb));
        }
        pB += PSTRIDE / 4;
        pC += PSTRIDE / 4;
        xcp += D_INNER;
        dtp += D_INNER;
        zp  += 2 * D_INNER;
        Yh  += D_INNER;
        Yl  += D_INNER;
    }
}

// ---------------- launch -----------------------------------------------------
extern "C" void kernel_launch(void* const* d_in, const int* in_sizes, int n_in,
                              void* d_out, int out_size)
{
    const float* x      = (const float*)d_in[0];
    const float* W_in   = (const float*)d_in[1];
    const float* conv_w = (const float*)d_in[2];
    const float* conv_b = (const float*)d_in[3];
    const float* W_x    = (const float*)d_in[4];
    const float* dt_w   = (const float*)d_in[5];
    const float* dt_b   = (const float*)d_in[6];
    const float* A_log  = (const float*)d_in[7];
    const float* D_par  = (const float*)d_in[8];
    const float* W_out  = (const float*)d_in[9];
    float* out = (float*)d_out;

    float *xz, *xc, *proj, *dtb_, *P, *Qc, *H;
    __nv_bfloat16 *xhi, *xlo, *w1hi, *w1lo, *w2hi, *w2lo, *yhi, *ylo;
    cudaGetSymbolAddress((void**)&xz,   g_xz);
    cudaGetSymbolAddress((void**)&xc,   g_xc);
    cudaGetSymbolAddress((void**)&proj, g_proj);
    cudaGetSymbolAddress((void**)&dtb_, g_dt);
    cudaGetSymbolAddress((void**)&P,    g_P);
    cudaGetSymbolAddress((void**)&Qc,   g_Qc);
    cudaGetSymbolAddress((void**)&H,    g_H);
    cudaGetSymbolAddress((void**)&xhi,  g_xhi);
    cudaGetSymbolAddress((void**)&xlo,  g_xlo);
    cudaGetSymbolAddress((void**)&w1hi, g_w1hi);
    cudaGetSymbolAddress((void**)&w1lo, g_w1lo);
    cudaGetSymbolAddress((void**)&w2hi, g_w2hi);
    cudaGetSymbolAddress((void**)&w2lo, g_w2lo);
    cudaGetSymbolAddress((void**)&yhi,  g_yhi);
    cudaGetSymbolAddress((void**)&ylo,  g_ylo);

    cudaFuncSetAttribute(mma_gemm_nt, cudaFuncAttributeMaxDynamicSharedMemorySize,
                         GEMM_SMEM);

    // 0) hi/lo splits
    {
        int n4;
        n4 = (M_TOT * D_MODEL) / 4;
        split_kernel<<<(n4 + 255) / 256, 256>>>(x, xhi, xlo, n4);
        n4 = (2 * D_INNER * D_MODEL) / 4;
        split_kernel<<<(n4 + 255) / 256, 256>>>(W_in, w1hi, w1lo, n4);
        n4 = (D_MODEL * D_INNER) / 4;
        split_kernel<<<(n4 + 255) / 256, 256>>>(W_out, w2hi, w2lo, n4);
    }
    // 1) xz = x @ W_in^T
    {
        dim3 grid(2 * D_INNER / 128, M_TOT / 128);
        mma_gemm_nt<<<grid, 256, GEMM_SMEM>>>(xhi, xlo, w1hi, w1lo, xz,
                                              M_TOT, 2 * D_INNER, D_MODEL);
    }
    // 2) conv + silu
    {
        int total = M_TOT * D_INNER;
        conv_silu_kernel<<<(total + 255) / 256, 256>>>(xz, conv_w, conv_b, xc);
    }
    // 3) proj = xc @ W_x^T (padded layout)
    {
        xproj_kernel<<<M_TOT / 8, 256>>>(xc, W_x, proj);
    }
    // 3b) dt precompute
    {
        int total = M_TOT * D_INNER;
        dt_kernel<<<(total + 255) / 256, 256>>>(proj, dt_w, dt_b, dtb_);
    }
    // 4) chunked scan (8 channels per warp)
    {
        int nwarp = (BSZ * D_INNER / 8) * CHUNKS;
        scan_pass1<<<nwarp / 8, 256>>>(proj, xc, dtb_, A_log, P, Qc);
        scan_pass2<<<(BSZ * D_INNER * D_STATE) / 256, 256>>>(P, Qc, H);
        scan_pass3<<<nwarp / 8, 256>>>(proj, xc, xz, dtb_, A_log, D_par,
                                       H, yhi, ylo);
    }
    // 5) out = Y @ W_out^T
    {
        dim3 grid(D_MODEL / 128, M_TOT / 128);
        mma_gemm_nt<<<grid, 256, GEMM_SMEM>>>(yhi, ylo, w2hi, w2lo, out,
                                              M_TOT, D_MODEL, D_INNER);
    }
}

// round 8
// speedup vs baseline: 3.6180x; 1.0783x over previous
#include <cuda_runtime.h>
#include <cuda_bf16.h>
#include <math.h>
#include <stdint.h>

#define D_MODEL 1024
#define D_STATE 16
#define D_INNER 2048
#define BSZ     2
#define LEN     1024
#define M_TOT   (BSZ*LEN)
#define NPROJ   (2*D_STATE+1)
#define PSTRIDE 36
#define CHUNKS  16
#define CHUNK_T (LEN/CHUNKS)

// ---------------- scratch --------------------------------------------------
__device__ float g_xz[(size_t)M_TOT * 2 * D_INNER];
__device__ float g_xc[(size_t)M_TOT * D_INNER];
__device__ float g_proj[(size_t)M_TOT * PSTRIDE];
__device__ float g_dt[(size_t)M_TOT * D_INNER];
__device__ float g_P [(size_t)BSZ * CHUNKS * D_INNER * D_STATE];
__device__ float g_Qc[(size_t)BSZ * CHUNKS * D_INNER * D_STATE];
__device__ float g_H [(size_t)BSZ * CHUNKS * D_INNER * D_STATE];
__device__ __nv_bfloat16 g_xhi[(size_t)M_TOT * D_MODEL];
__device__ __nv_bfloat16 g_xlo[(size_t)M_TOT * D_MODEL];
__device__ __nv_bfloat16 g_w1hi[(size_t)2 * D_INNER * D_MODEL];
__device__ __nv_bfloat16 g_w1lo[(size_t)2 * D_INNER * D_MODEL];
__device__ __nv_bfloat16 g_w2hi[(size_t)D_MODEL * D_INNER];
__device__ __nv_bfloat16 g_w2lo[(size_t)D_MODEL * D_INNER];
__device__ __nv_bfloat16 g_yhi[(size_t)M_TOT * D_INNER];
__device__ __nv_bfloat16 g_ylo[(size_t)M_TOT * D_INNER];

// ---------------- helpers ----------------------------------------------------
__device__ __forceinline__ uint32_t smem_u32(const void* p) {
    uint32_t a;
    asm("{ .reg .u64 t; cvta.to.shared.u64 t, %1; cvt.u32.u64 %0, t; }"
        : "=r"(a) : "l"(p));
    return a;
}
// 64B-row swizzle: row r, 16B segment c (0..3) -> byte offset
__device__ __forceinline__ uint32_t sw64(int r, int c) {
    return (uint32_t)(r * 64 + ((c ^ ((r >> 1) & 3)) << 4));
}
__device__ __forceinline__ uint32_t pack_bf2(float f0, float f1) {
    uint32_t r;
    asm("cvt.rn.bf16x2.f32 %0, %1, %2;" : "=r"(r) : "f"(f1), "f"(f0));
    return r;
}
__device__ __forceinline__ void ldsm4(uint32_t* r, uint32_t addr) {
    asm volatile("ldmatrix.sync.aligned.m8n8.x4.shared.b16 {%0,%1,%2,%3}, [%4];"
        : "=r"(r[0]), "=r"(r[1]), "=r"(r[2]), "=r"(r[3]) : "r"(addr));
}
__device__ __forceinline__ void mma_bf16(float* d, const uint32_t* a,
                                         const uint32_t* b) {
    asm volatile(
        "mma.sync.aligned.m16n8k16.row.col.f32.bf16.bf16.f32 "
        "{%0,%1,%2,%3}, {%4,%5,%6,%7}, {%8,%9}, {%0,%1,%2,%3};"
        : "+f"(d[0]), "+f"(d[1]), "+f"(d[2]), "+f"(d[3])
        : "r"(a[0]), "r"(a[1]), "r"(a[2]), "r"(a[3]), "r"(b[0]), "r"(b[1]));
}
__device__ __forceinline__ void cp16(uint32_t dst, const void* src) {
    asm volatile("cp.async.cg.shared.global [%0], [%1], 16;"
                 :: "r"(dst), "l"(src));
}

// ---------------- hi/lo split ------------------------------------------------
__global__ void split_kernel(const float* __restrict__ in,
                             __nv_bfloat16* __restrict__ hi,
                             __nv_bfloat16* __restrict__ lo, int n4)
{
    int i = blockIdx.x * blockDim.x + threadIdx.x;
    if (i >= n4) return;
    float4 v = ((const float4*)in)[i];
    float hx = __bfloat162float(__float2bfloat16(v.x));
    float hy = __bfloat162float(__float2bfloat16(v.y));
    float hz = __bfloat162float(__float2bfloat16(v.z));
    float hw = __bfloat162float(__float2bfloat16(v.w));
    uint2 h, l;
    h.x = pack_bf2(v.x, v.y);  h.y = pack_bf2(v.z, v.w);
    l.x = pack_bf2(v.x - hx, v.y - hy);
    l.y = pack_bf2(v.z - hz, v.w - hw);
    ((uint2*)hi)[i] = h;
    ((uint2*)lo)[i] = l;
}

// ---------------- mma.sync GEMM (NT), K-chunk 32, 3 stages, 2 CTAs/SM ---------
#define OFF_AHI 0
#define OFF_ALO 8192
#define OFF_BHI 16384
#define OFF_BLO 24576
#define STAGE_BYTES 32768
#define STAGES 3
#define GEMM_SMEM (1024 + STAGES*STAGE_BYTES)

__global__ void __launch_bounds__(256, 2)
mma_gemm_nt(const __nv_bfloat16* __restrict__ Ahi, const __nv_bfloat16* __restrict__ Alo,
            const __nv_bfloat16* __restrict__ Bhi, const __nv_bfloat16* __restrict__ Blo,
            float* __restrict__ C, int M, int N, int K)
{
    extern __shared__ char smc[];
    const uint32_t smb0 = smem_u32(smc);
    const uint32_t smb  = (smb0 + 1023) & ~1023u;

    const int tid = threadIdx.x, wid = tid >> 5, lane = tid & 31;
    const int row0 = blockIdx.y * 128, col0 = blockIdx.x * 128;
    const int wm = (wid & 3) * 32;
    const int wn = (wid >> 2) * 64;

    float acc[2][8][4];
    #pragma unroll
    for (int a = 0; a < 2; a++)
        #pragma unroll
        for (int b = 0; b < 8; b++)
            #pragma unroll
            for (int c = 0; c < 4; c++) acc[a][b][c] = 0.f;

    const int lj = lane >> 3;
    const int lr = lane & 7;
    const int nchunk = K >> 5;

    auto load_chunk = [&](int kc, int stage) {
        const __nv_bfloat16* pAh = Ahi + (size_t)row0 * K + kc * 32;
        const __nv_bfloat16* pAl = Alo + (size_t)row0 * K + kc * 32;
        const __nv_bfloat16* pBh = Bhi + (size_t)col0 * K + kc * 32;
        const __nv_bfloat16* pBl = Blo + (size_t)col0 * K + kc * 32;
        uint32_t sb = smb + stage * STAGE_BYTES;
        #pragma unroll
        for (int i = 0; i < 2; i++) {
            int ch = tid + 256 * i;           // 0..511 16B-chunks per array
            int r = ch >> 2, c = ch & 3;
            uint32_t so = sw64(r, c);
            size_t g = (size_t)r * K + c * 8;
            cp16(sb + OFF_AHI + so, pAh + g);
            cp16(sb + OFF_ALO + so, pAl + g);
            cp16(sb + OFF_BHI + so, pBh + g);
            cp16(sb + OFF_BLO + so, pBl + g);
        }
        asm volatile("cp.async.commit_group;" ::: "memory");
    };

    load_chunk(0, 0);
    if (nchunk > 1) load_chunk(1, 1);

    for (int kc = 0; kc < nchunk; kc++) {
        asm volatile("cp.async.wait_group %0;" :: "n"(STAGES - 2) : "memory");
        __syncthreads();
        if (kc + STAGES - 1 < nchunk)
            load_chunk(kc + STAGES - 1, (kc + STAGES - 1) % STAGES);

        uint32_t sb = smb + (kc % STAGES) * STAGE_BYTES;
        #pragma unroll
        for (int ks = 0; ks < 2; ks++) {
            uint32_t ah[2][4], al[2][4];
            #pragma unroll
            for (int mt = 0; mt < 2; mt++) {
                int rr = wm + mt * 16 + (lj & 1) * 8 + lr;
                int cseg = ks * 2 + (lj >> 1);
                uint32_t so = sw64(rr, cseg);
                ldsm4(ah[mt], sb + OFF_AHI + so);
                ldsm4(al[mt], sb + OFF_ALO + so);
            }
            uint32_t bh[4][4], bl[4][4];
            #pragma unroll
            for (int np = 0; np < 4; np++) {
                int rr = wn + np * 16 + (lj >> 1) * 8 + lr;
                int cseg = ks * 2 + (lj & 1);
                uint32_t so = sw64(rr, cseg);
                ldsm4(bh[np], sb + OFF_BHI + so);
                ldsm4(bl[np], sb + OFF_BLO + so);
            }
            #pragma unroll
            for (int mt = 0; mt < 2; mt++)
                #pragma unroll
                for (int np = 0; np < 4; np++) {
                    mma_bf16(acc[mt][2*np+0], ah[mt], &bh[np][0]);
                    mma_bf16(acc[mt][2*np+1], ah[mt], &bh[np][2]);
                }
            #pragma unroll
            for (int mt = 0; mt < 2; mt++)
                #pragma unroll
                for (int np = 0; np < 4; np++) {
                    mma_bf16(acc[mt][2*np+0], ah[mt], &bl[np][0]);
                    mma_bf16(acc[mt][2*np+1], ah[mt], &bl[np][2]);
                }
            #pragma unroll
            for (int mt = 0; mt < 2; mt++)
                #pragma unroll
                for (int np = 0; np < 4; np++) {
                    mma_bf16(acc[mt][2*np+0], al[mt], &bh[np][0]);
                    mma_bf16(acc[mt][2*np+1], al[mt], &bh[np][2]);
                }
        }
    }

    #pragma unroll
    for (int mt = 0; mt < 2; mt++) {
        int row = row0 + wm + mt * 16 + (lane >> 2);
        #pragma unroll
        for (int nt = 0; nt < 8; nt++) {
            int col = col0 + wn + nt * 8 + 2 * (lane & 3);
            float2 v0 = make_float2(acc[mt][nt][0], acc[mt][nt][1]);
            float2 v1 = make_float2(acc[mt][nt][2], acc[mt][nt][3]);
            *(float2*)(C + (size_t)row * N + col) = v0;
            *(float2*)(C + (size_t)(row + 8) * N + col) = v1;
        }
    }
}

// ---------------- causal depthwise conv (K=4) + SiLU ------------------------
__global__ void conv_silu_kernel(const float* __restrict__ xz,
                                 const float* __restrict__ cw,
                                 const float* __restrict__ cb,
                                 float* __restrict__ xc)
{
    int idx = blockIdx.x * blockDim.x + threadIdx.x;
    if (idx >= M_TOT * D_INNER) return;
    int d = idx & (D_INNER - 1);
    int m = idx >> 11;
    int l = m & (LEN - 1);

    const float w0 = cw[d * 4 + 0], w1 = cw[d * 4 + 1];
    const float w2 = cw[d * 4 + 2], w3 = cw[d * 4 + 3];
    const float* base = xz + (size_t)m * (2 * D_INNER) + d;
    const int stride = 2 * D_INNER;

    float acc = cb[d] + w3 * base[0];
    if (l >= 1) acc += w2 * base[-stride];
    if (l >= 2) acc += w1 * base[-2 * stride];
    if (l >= 3) acc += w0 * base[-3 * stride];

    float sig = 1.f / (1.f + __expf(-acc));
    xc[idx] = acc * sig;
}

// ---------------- x-proj: Wx staged through SMEM (8 warps share) --------------
#define XPC 256   // K-chunk (floats)
__global__ void __launch_bounds__(256)
xproj_kernel(const float* __restrict__ xc, const float* __restrict__ Wx,
             float* __restrict__ proj)
{
    __shared__ float ws[NPROJ][XPC];   // 33*256*4 = 33.8KB
    int tid  = threadIdx.x;
    int warp = tid >> 5;
    int lane = tid & 31;
    int row  = blockIdx.x * 8 + warp;

    const float* xr = xc + (size_t)row * D_INNER;
    float acc[NPROJ];
    #pragma unroll
    for (int e = 0; e < NPROJ; e++) acc[e] = 0.f;

    for (int kc = 0; kc < D_INNER; kc += XPC) {
        __syncthreads();
        // cooperative stage of Wx[:, kc:kc+XPC]
        for (int idx = tid; idx < NPROJ * (XPC / 4); idx += 256) {
            int e  = idx / (XPC / 4);
            int k4 = idx % (XPC / 4);
            ((float4*)ws[e])[k4] =
                ((const float4*)(Wx + (size_t)e * D_INNER + kc))[k4];
        }
        __syncthreads();
        #pragma unroll
        for (int it = 0; it < XPC / 4 / 32; it++) {
            int k4 = it * 32 + lane;
            float4 xv = ((const float4*)(xr + kc))[k4];
            #pragma unroll
            for (int e = 0; e < NPROJ; e++) {
                float4 wv = ((const float4*)ws[e])[k4];
                acc[e] += fmaf(xv.x, wv.x, fmaf(xv.y, wv.y,
                          fmaf(xv.z, wv.z, xv.w * wv.w)));
            }
        }
    }
    #pragma unroll
    for (int e = 0; e < NPROJ; e++) {
        float v = acc[e];
        v += __shfl_xor_sync(0xffffffffu, v, 16);
        v += __shfl_xor_sync(0xffffffffu, v, 8);
        v += __shfl_xor_sync(0xffffffffu, v, 4);
        v += __shfl_xor_sync(0xffffffffu, v, 2);
        v += __shfl_xor_sync(0xffffffffu, v, 1);
        int off = (e == 0) ? 0 : (e + 3);
        if (lane == (e & 31)) proj[(size_t)row * PSTRIDE + off] = v;
    }
}

// ---------------- dt precompute ------------------------------------------------
__global__ void dt_kernel(const float* __restrict__ proj,
                          const float* __restrict__ dt_w,
                          const float* __restrict__ dt_b,
                          float* __restrict__ dt)
{
    int idx = blockIdx.x * blockDim.x + threadIdx.x;
    if (idx >= M_TOT * D_INNER) return;
    int d = idx & (D_INNER - 1);
    int m = idx >> 11;
    float s = fmaf(proj[(size_t)m * PSTRIDE], dt_w[d], dt_b[d]);
    dt[idx] = (s > 20.f) ? s : log1pf(__expf(s));
}

// ---------------- chunked selective scan -------------------------------------
__global__ void __launch_bounds__(256)
scan_pass1(const float* __restrict__ proj, const float* __restrict__ xc,
           const float* __restrict__ dt, const float* __restrict__ A_log,
           float* __restrict__ P, float* __restrict__ Q)
{
    int wg   = (blockIdx.x * blockDim.x + threadIdx.x) >> 5;
    int lane = threadIdx.x & 31;
    int grp  = wg >> 4;
    int c    = wg & (CHUNKS - 1);
    if (grp >= BSZ * D_INNER / 8) return;
    int ch = lane >> 2, sg = lane & 3, n0 = sg * 4;
    int q  = grp * 8 + ch;
    int b  = q >> 11;
    int d  = q & (D_INNER - 1);

    float4 al = *(const float4*)(A_log + d * D_STATE + n0);
    float An0 = -expf(al.x), An1 = -expf(al.y);
    float An2 = -expf(al.z), An3 = -expf(al.w);

    const int m0 = b * LEN + c * CHUNK_T;
    const float4* pB  = (const float4*)(proj + (size_t)m0 * PSTRIDE + 4 + n0);
    const float*  xcp = xc + (size_t)m0 * D_INNER + d;
    const float*  dtp = dt + (size_t)m0 * D_INNER + d;

    float h0 = 0.f, h1 = 0.f, h2 = 0.f, h3 = 0.f;
    float P0 = 1.f, P1 = 1.f, P2 = 1.f, P3 = 1.f;

    #pragma unroll 4
    for (int t = 0; t < CHUNK_T; t++) {
        float4 Bv = *pB;
        float xcv = *xcp, dtv = *dtp;
        float u = dtv * xcv;
        float dA0 = __expf(dtv * An0);
        float dA1 = __expf(dtv * An1);
        float dA2 = __expf(dtv * An2);
        float dA3 = __expf(dtv * An3);
        h0 = fmaf(dA0, h0, u * Bv.x);  P0 *= dA0;
        h1 = fmaf(dA1, h1, u * Bv.y);  P1 *= dA1;
        h2 = fmaf(dA2, h2, u * Bv.z);  P2 *= dA2;
        h3 = fmaf(dA3, h3, u * Bv.w);  P3 *= dA3;
        pB += PSTRIDE / 4;
        xcp += D_INNER;
        dtp += D_INNER;
    }
    size_t o = ((size_t)((b * CHUNKS + c) * D_INNER) + d) * D_STATE + n0;
    *(float4*)(P + o) = make_float4(P0, P1, P2, P3);
    *(float4*)(Q + o) = make_float4(h0, h1, h2, h3);
}

__global__ void __launch_bounds__(256)
scan_pass2(const float* __restrict__ P, const float* __restrict__ Q,
           float* __restrict__ H)
{
    int i = blockIdx.x * blockDim.x + threadIdx.x;
    if (i >= BSZ * D_INNER * D_STATE) return;
    int n = i & 15;
    int d = (i >> 4) & (D_INNER - 1);
    int b = i >> 15;

    float h = 0.f;
    #pragma unroll
    for (int c = 0; c < CHUNKS; c++) {
        size_t o = ((size_t)((b * CHUNKS + c) * D_INNER) + d) * D_STATE + n;
        H[o] = h;
        h = fmaf(P[o], h, Q[o]);
    }
}

__global__ void __launch_bounds__(256)
scan_pass3(const float* __restrict__ proj, const float* __restrict__ xc,
           const float* __restrict__ xz, const float* __restrict__ dt,
           const float* __restrict__ A_log, const float* __restrict__ Dp,
           const float* __restrict__ H,
           __nv_bfloat16* __restrict__ Yhi, __nv_bfloat16* __restrict__ Ylo)
{
    int wg   = (blockIdx.x * blockDim.x + threadIdx.x) >> 5;
    int lane = threadIdx.x & 31;
    int grp  = wg >> 4;
    int c    = wg & (CHUNKS - 1);
    if (grp >= BSZ * D_INNER / 8) return;
    int ch = lane >> 2, sg = lane & 3, n0 = sg * 4;
    int q  = grp * 8 + ch;
    int b  = q >> 11;
    int d  = q & (D_INNER - 1);

    float4 al = *(const float4*)(A_log + d * D_STATE + n0);
    float An0 = -expf(al.x), An1 = -expf(al.y);
    float An2 = -expf(al.z), An3 = -expf(al.w);
    const float Dd = Dp[d];

    float4 hv4 = *(const float4*)(H + ((size_t)((b * CHUNKS + c) * D_INNER) + d) * D_STATE + n0);
    float h0 = hv4.x, h1 = hv4.y, h2 = hv4.z, h3 = hv4.w;

    const int m0 = b * LEN + c * CHUNK_T;
    const float4* pB  = (const float4*)(proj + (size_t)m0 * PSTRIDE + 4 + n0);
    const float4* pC  = (const float4*)(proj + (size_t)m0 * PSTRIDE + 20 + n0);
    const float*  xcp = xc + (size_t)m0 * D_INNER + d;
    const float*  dtp = dt + (size_t)m0 * D_INNER + d;
    const float*  zp  = xz + (size_t)m0 * (2 * D_INNER) + D_INNER + d;
    __nv_bfloat16* Yh = Yhi + (size_t)m0 * D_INNER + d;
    __nv_bfloat16* Yl = Ylo + (size_t)m0 * D_INNER + d;

    #pragma unroll 2
    for (int t = 0; t < CHUNK_T; t++) {
        float4 Bv = *pB;
        float4 Cv = *pC;
        float xcv = *xcp, dtv = *dtp, zv = *zp;
        float u = dtv * xcv;
        float dA0 = __expf(dtv * An0);
        float dA1 = __expf(dtv * An1);
        float dA2 = __expf(dtv * An2);
        float dA3 = __expf(dtv * An3);
        h0 = fmaf(dA0, h0, u * Bv.x);
        h1 = fmaf(dA1, h1, u * Bv.y);
        h2 = fmaf(dA2, h2, u * Bv.z);
        h3 = fmaf(dA3, h3, u * Bv.w);

        float y = fmaf(h0, Cv.x, fmaf(h1, Cv.y, fmaf(h2, Cv.z, h3 * Cv.w)));
        y += __shfl_xor_sync(0xffffffffu, y, 1);
        y += __shfl_xor_sync(0xffffffffu, y, 2);

        if (sg == 0) {
            float sig = 1.f / (1.f + __expf(-zv));
            float yv = (y + xcv * Dd) * (zv * sig);
            __nv_bfloat16 hb = __float2bfloat16(yv);
            *Yh = hb;
            *Yl = __float2bfloat16(yv - __bfloat162float(hb));
        }
        pB += PSTRIDE / 4;
        pC += PSTRIDE / 4;
        xcp += D_INNER;
        dtp += D_INNER;
        zp  += 2 * D_INNER;
        Yh  += D_INNER;
        Yl  += D_INNER;
    }
}

// ---------------- launch -----------------------------------------------------
extern "C" void kernel_launch(void* const* d_in, const int* in_sizes, int n_in,
                              void* d_out, int out_size)
{
    const float* x      = (const float*)d_in[0];
    const float* W_in   = (const float*)d_in[1];
    const float* conv_w = (const float*)d_in[2];
    const float* conv_b = (const float*)d_in[3];
    const float* W_x    = (const float*)d_in[4];
    const float* dt_w   = (const float*)d_in[5];
    const float* dt_b   = (const float*)d_in[6];
    const float* A_log  = (const float*)d_in[7];
    const float* D_par  = (const float*)d_in[8];
    const float* W_out  = (const float*)d_in[9];
    float* out = (float*)d_out;

    float *xz, *xc, *proj, *dtb_, *P, *Qc, *H;
    __nv_bfloat16 *xhi, *xlo, *w1hi, *w1lo, *w2hi, *w2lo, *yhi, *ylo;
    cudaGetSymbolAddress((void**)&xz,   g_xz);
    cudaGetSymbolAddress((void**)&xc,   g_xc);
    cudaGetSymbolAddress((void**)&proj, g_proj);
    cudaGetSymbolAddress((void**)&dtb_, g_dt);
    cudaGetSymbolAddress((void**)&P,    g_P);
    cudaGetSymbolAddress((void**)&Qc,   g_Qc);
    cudaGetSymbolAddress((void**)&H,    g_H);
    cudaGetSymbolAddress((void**)&xhi,  g_xhi);
    cudaGetSymbolAddress((void**)&xlo,  g_xlo);
    cudaGetSymbolAddress((void**)&w1hi, g_w1hi);
    cudaGetSymbolAddress((void**)&w1lo, g_w1lo);
    cudaGetSymbolAddress((void**)&w2hi, g_w2hi);
    cudaGetSymbolAddress((void**)&w2lo, g_w2lo);
    cudaGetSymbolAddress((void**)&yhi,  g_yhi);
    cudaGetSymbolAddress((void**)&ylo,  g_ylo);

    cudaFuncSetAttribute(mma_gemm_nt, cudaFuncAttributeMaxDynamicSharedMemorySize,
                         GEMM_SMEM);

    // 0) hi/lo splits
    {
        int n4;
        n4 = (M_TOT * D_MODEL) / 4;
        split_kernel<<<(n4 + 255) / 256, 256>>>(x, xhi, xlo, n4);
        n4 = (2 * D_INNER * D_MODEL) / 4;
        split_kernel<<<(n4 + 255) / 256, 256>>>(W_in, w1hi, w1lo, n4);
        n4 = (D_MODEL * D_INNER) / 4;
        split_kernel<<<(n4 + 255) / 256, 256>>>(W_out, w2hi, w2lo, n4);
    }
    // 1) xz = x @ W_in^T
    {
        dim3 grid(2 * D_INNER / 128, M_TOT / 128);
        mma_gemm_nt<<<grid, 256, GEMM_SMEM>>>(xhi, xlo, w1hi, w1lo, xz,
                                              M_TOT, 2 * D_INNER, D_MODEL);
    }
    // 2) conv + silu
    {
        int total = M_TOT * D_INNER;
        conv_silu_kernel<<<(total + 255) / 256, 256>>>(xz, conv_w, conv_b, xc);
    }
    // 3) proj = xc @ W_x^T (Wx staged in smem)
    {
        xproj_kernel<<<M_TOT / 8, 256>>>(xc, W_x, proj);
    }
    // 3b) dt precompute
    {
        int total = M_TOT * D_INNER;
        dt_kernel<<<(total + 255) / 256, 256>>>(proj, dt_w, dt_b, dtb_);
    }
    // 4) chunked scan
    {
        int nwarp = (BSZ * D_INNER / 8) * CHUNKS;
        scan_pass1<<<nwarp / 8, 256>>>(proj, xc, dtb_, A_log, P, Qc);
        scan_pass2<<<(BSZ * D_INNER * D_STATE) / 256, 256>>>(P, Qc, H);
        scan_pass3<<<nwarp / 8, 256>>>(proj, xc, xz, dtb_, A_log, D_par,
                                       H, yhi, ylo);
    }
    // 5) out = Y @ W_out^T
    {
        dim3 grid(D_MODEL / 128, M_TOT / 128);
        mma_gemm_nt<<<grid, 256, GEMM_SMEM>>>(yhi, ylo, w2hi, w2lo, out,
                                              M_TOT, D_MODEL, D_INNER);
    }
}